// round 13
// baseline (speedup 1.0000x reference)
#include <cuda_runtime.h>
#include <cuda_bf16.h>
#include <cuda_fp8.h>
#include <math.h>

#define NN 4096
#define ALPHA 0.2f

__device__ __forceinline__ float lrelu(float v){ return v >= 0.f ? v : ALPHA * v; }

// monotone float<->uint encoding for atomicMax
__device__ __forceinline__ unsigned encf(float f) {
    unsigned b = __float_as_uint(f);
    return b ^ ((b & 0x80000000u) ? 0xFFFFFFFFu : 0x80000000u);
}
__device__ __forceinline__ float decf(unsigned u) {
    unsigned b = u ^ ((u & 0x80000000u) ? 0x80000000u : 0xFFFFFFFFu);
    return __uint_as_float(b);
}

// ---------------- scratch arenas (device globals; no allocation) -------------
#define OFF_P0    0L
#define OFF_P1    4096L
#define OFF_OWH   8192L
#define OFF_HO0   270336L
#define OFF_WHC   532480L
#define OFF_HOUT  536576L
#define OFF_S1V   540672L
#define OFF_S2V   557056L
#define OFF_M     573440L
#define OFF_DV    573456L
#define OFF_S1O   577552L
#define OFF_S2O   581648L
#define OFF_WHB   585744L     // fp8 4*4096*256 bytes
#define OFF_HINB  1634320L    // bf16 4096*512
#define OFF_H1B   2682896L    // bf16 4*4096*256
#define OFF_HCATB 4780048L    // bf16 4096*1024
#define OFF_W0B   6877200L
#define OFF_W1B   7139344L
#define OFF_WO0B  7270416L
#define OFF_PART  7303184L
#define FARENA_SZ 8400000L

#define OFF_CNT   0
#define OFF_RP    4096
#define OFF_MSK   8208
#define OFF_CI    532496
#define OFF_AMAX  2190000     // 4 encoded-max slots
#define IARENA_SZ 2200000

__device__ float g_farena[FARENA_SZ];
__device__ int   g_iarena[IARENA_SZ];

// ---------------- fused count (adj bitmask) + rowsum (s_mat degree) ----------
__global__ void k_cnt_rs(const float* __restrict__ adj, unsigned* __restrict__ msk,
                         int* __restrict__ cnt,
                         const float* __restrict__ smat, float* __restrict__ dv) {
    int row = blockIdx.x, tid = threadIdx.x;
    int lane = tid & 31, wid = tid >> 5;
    const float4* p = reinterpret_cast<const float4*>(adj + (long)row * NN);
    unsigned* mrow = msk + (long)row * 128;
    int c = 0;
    for (int seg = wid; seg < 32; seg += 8) {
        float4 v = p[seg * 32 + lane];
        unsigned b0 = __ballot_sync(0xFFFFFFFFu, v.x > 0.f);
        unsigned b1 = __ballot_sync(0xFFFFFFFFu, v.y > 0.f);
        unsigned b2 = __ballot_sync(0xFFFFFFFFu, v.z > 0.f);
        unsigned b3 = __ballot_sync(0xFFFFFFFFu, v.w > 0.f);
        c += (v.x > 0.f) + (v.y > 0.f) + (v.z > 0.f) + (v.w > 0.f);
        if (lane == 0) {
            mrow[seg * 4 + 0] = b0; mrow[seg * 4 + 1] = b1;
            mrow[seg * 4 + 2] = b2; mrow[seg * 4 + 3] = b3;
        }
    }
    const float4* q = reinterpret_cast<const float4*>(smat + (long)row * NN);
    float a = 0.f;
    for (int i = tid; i < NN / 4; i += 256) { float4 v = q[i]; a += v.x + v.y + v.z + v.w; }
    for (int o = 16; o; o >>= 1) {
        c += __shfl_xor_sync(0xFFFFFFFFu, c, o);
        a += __shfl_xor_sync(0xFFFFFFFFu, a, o);
    }
    __shared__ int ws[8];
    __shared__ float fs[8];
    if (lane == 0) { ws[wid] = c; fs[wid] = a; }
    __syncthreads();
    if (tid == 0)
        cnt[row] = ws[0] + ws[1] + ws[2] + ws[3] + ws[4] + ws[5] + ws[6] + ws[7];
    if (tid == 32)
        dv[row] = fs[0] + fs[1] + fs[2] + fs[3] + fs[4] + fs[5] + fs[6] + fs[7];
}

__global__ void k_scan(const int* __restrict__ cnt, int* __restrict__ rp) {
    __shared__ int s[1024];
    int t = threadIdx.x;
    int v[4]; int loc = 0;
#pragma unroll
    for (int k = 0; k < 4; k++) { v[k] = cnt[t * 4 + k]; loc += v[k]; }
    s[t] = loc; __syncthreads();
    for (int off = 1; off < 1024; off <<= 1) {
        int add = (t >= off) ? s[t - off] : 0;
        __syncthreads();
        s[t] += add;
        __syncthreads();
    }
    int run = (t == 0) ? 0 : s[t - 1];
#pragma unroll
    for (int k = 0; k < 4; k++) { rp[t * 4 + k] = run; run += v[k]; }
    if (t == 1023) rp[NN] = run;
}

__global__ void k_fill(const unsigned* __restrict__ msk, const int* __restrict__ rp,
                       int* __restrict__ ci) {
    int row = blockIdx.x, tid = threadIdx.x;
    int lane = tid & 31, wid = tid >> 5;
    unsigned m = msk[(long)row * 128 + tid];
    int c = __popc(m);
    int pre = c;
    for (int o = 1; o < 32; o <<= 1) {
        int v = __shfl_up_sync(0xFFFFFFFFu, pre, o);
        if (lane >= o) pre += v;
    }
    __shared__ int wt[4];
    if (lane == 31) wt[wid] = pre;
    __syncthreads();
    int woff = 0;
    for (int i = 0; i < wid; i++) woff += wt[i];
    int pos = rp[row] + woff + pre - c;
    int base = (tid >> 2) * 128 + (tid & 3);
    while (m) {
        int b = __ffs(m) - 1;
        m &= m - 1;
        ci[pos++] = base + b * 4;
    }
}

// ---------------- fused prep: merge->bf16 + 3 weight cvts + amax reset -------
__device__ __forceinline__ uint2 pack_bf16x4(float4 v) {
    __nv_bfloat162 p0 = __float22bfloat162_rn(make_float2(v.x, v.y));
    __nv_bfloat162 p1 = __float22bfloat162_rn(make_float2(v.z, v.w));
    uint2 w;
    w.x = *reinterpret_cast<unsigned int*>(&p0);
    w.y = *reinterpret_cast<unsigned int*>(&p1);
    return w;
}

__global__ void k_prep(const float4* __restrict__ x, const int* __restrict__ obs,
                       const float4* __restrict__ theta, uint2* __restrict__ hinb,
                       const float4* __restrict__ w0, uint2* __restrict__ o0,
                       const float4* __restrict__ w1, uint2* __restrict__ o1,
                       const float4* __restrict__ w2, uint2* __restrict__ o2,
                       unsigned* __restrict__ amax) {
    long i = (long)blockIdx.x * 256 + threadIdx.x;
    if (i < 4) amax[i] = encf(-1e30f);
    if (i < 524288L) {
        int row = (int)(i >> 7);
        int f4 = (int)(i & 127);
        float4 v = x[i];
        if (obs[row] == 1) {
            float4 t = theta[f4];
            v.x += t.x; v.y += t.y; v.z += t.z; v.w += t.w;
        }
        hinb[i] = pack_bf16x4(v);
        return;
    }
    i -= 524288L;
    if (i < 131072) { o0[i] = pack_bf16x4(w0[i]); return; }
    i -= 131072;
    if (i < 65536) { o1[i] = pack_bf16x4(w1[i]); return; }
    i -= 65536;
    if (i < 16384) { o2[i] = pack_bf16x4(w2[i]); }
}

// ---------------- fused W@a for both layers ----------------
__global__ void k_wa2(const float* __restrict__ W0, const float* __restrict__ a0,
                      float* __restrict__ P0,
                      const float* __restrict__ W1, const float* __restrict__ a1,
                      float* __restrict__ P1) {
    int h = blockIdx.y;
    int bx = blockIdx.x;
    const float* W; const float* a; float* P; int Fin;
    if (bx < 128) { W = W0; a = a0; P = P0; Fin = 512; }
    else { W = W1; a = a1; P = P1; Fin = 256; bx -= 128; }
    int idx = bx * 8 + (threadIdx.x >> 5);
    int lane = threadIdx.x & 31;
    if (idx >= 2 * Fin) return;
    int c = idx / Fin, f = idx % Fin;
    const float* wrow = W + ((long)h * Fin + f) * 256;
    const float* av = a + h * 512 + c * 256;
    float d = 0.f;
    for (int k = lane; k < 256; k += 32) d = fmaf(wrow[k], av[k], d);
    for (int o = 16; o; o >>= 1) d += __shfl_xor_sync(0xFFFFFFFFu, d, o);
    if (lane == 0) P[(2 * h + c) * Fin + f] = d;
}

// s1/s2 from bf16 activations -> interleaved [row][head]
__global__ void __launch_bounds__(256) k_sb(
    const __nv_bfloat16* __restrict__ act, long headStride,
    const float* __restrict__ P, int K,
    float* __restrict__ s1, float* __restrict__ s2) {
    __shared__ float Ps[4096];
    int tid = threadIdx.x;
    for (int i = tid; i < 8 * K; i += 256) Ps[i] = P[i];
    __syncthreads();
    int gw = blockIdx.x * 8 + (tid >> 5);
    int lane = tid & 31;
    int row = gw >> 2, h = gw & 3;
    const __nv_bfloat16* a = act + (long)h * headStride + (long)row * K;
    const float* p1 = Ps + (2 * h) * K;
    const float* p2 = p1 + K;
    float d1 = 0.f, d2 = 0.f;
    for (int f = lane * 2; f < K; f += 64) {
        unsigned u = *reinterpret_cast<const unsigned*>(a + f);
        float x0 = __uint_as_float(u << 16);
        float x1 = __uint_as_float(u & 0xFFFF0000u);
        d1 = fmaf(x0, p1[f], fmaf(x1, p1[f + 1], d1));
        d2 = fmaf(x0, p2[f], fmaf(x1, p2[f + 1], d2));
    }
    for (int o = 16; o; o >>= 1) {
        d1 += __shfl_xor_sync(0xFFFFFFFFu, d1, o);
        d2 += __shfl_xor_sync(0xFFFFFFFFu, d2, o);
    }
    if (lane == 0) { s1[gw] = d1; s2[gw] = d2; }
}

// fused split-K reduce + bf16 oWh + s projection + atomic max (out layer 0)
__global__ void k_red4s(const float2* __restrict__ part,
                        __nv_bfloat162* __restrict__ oWhb,
                        const float* __restrict__ ao0,
                        float* __restrict__ s1, float* __restrict__ s2,
                        unsigned* __restrict__ amax) {
    int gw = blockIdx.x * 8 + (threadIdx.x >> 5);
    int lane = threadIdx.x & 31;
    long idx = (long)gw * 32 + lane;
    float2 v0 = part[idx];
    float2 v1 = part[idx + 131072];
    float2 v2 = part[idx + 262144];
    float2 v3 = part[idx + 393216];
    float2 s;
    s.x = v0.x + v1.x + v2.x + v3.x;
    s.y = v0.y + v1.y + v2.y + v3.y;
    oWhb[idx] = __float22bfloat162_rn(s);
    float d1 = s.x * ao0[lane * 2] + s.y * ao0[lane * 2 + 1];
    float d2 = s.x * ao0[64 + lane * 2] + s.y * ao0[64 + lane * 2 + 1];
    for (int o = 16; o; o >>= 1) {
        d1 += __shfl_xor_sync(0xFFFFFFFFu, d1, o);
        d2 += __shfl_xor_sync(0xFFFFFFFFu, d2, o);
    }
    if (lane == 0) {
        s1[gw] = d1; s2[gw] = d2;
        atomicMax(&amax[0], encf(d1));
        atomicMax(&amax[1], encf(d2));
    }
}

// per-head M = leaky(max s1 + max s2); stride-indexed (head layers only)
__global__ void k_max4(const float* __restrict__ s1, const float* __restrict__ s2,
                       float* __restrict__ Mp, int stride) {
    int h = blockIdx.x;
    __shared__ float m1s[512], m2s[512];
    int t = threadIdx.x;
    float m1 = -1e30f, m2 = -1e30f;
    for (int i = t; i < NN; i += 512) {
        m1 = fmaxf(m1, s1[i * stride + h]);
        m2 = fmaxf(m2, s2[i * stride + h]);
    }
    m1s[t] = m1; m2s[t] = m2; __syncthreads();
    for (int s = 256; s; s >>= 1) {
        if (t < s) { m1s[t] = fmaxf(m1s[t], m1s[t + s]); m2s[t] = fmaxf(m2s[t], m2s[t + s]); }
        __syncthreads();
    }
    if (t == 0) Mp[h] = lrelu(m1s[0] + m2s[0]);
}

// ---------- fused 4-head FP8 aggregation: 8-deep software pipeline -----------
__global__ void __launch_bounds__(256, 4) k_agg4(
    const unsigned char* __restrict__ Whb,
    const float4* __restrict__ s1v, const float4* __restrict__ s2v,
    const float* __restrict__ Mp,
    const int* __restrict__ rp, const int* __restrict__ ci,
    __nv_bfloat16* __restrict__ outBase, long headStride, int ostride) {
    int row = blockIdx.x;
    int tid = threadIdx.x;
    int lane = tid & 31, warp = tid >> 5;
    int h = warp >> 1, par = warp & 1;

    __shared__ float4   swp[392];
    __shared__ unsigned soff[392];
    __shared__ float    sacc[8][256];
    __shared__ float    szw[8];

    int rs = rp[row], re = rp[row + 1];
    float4 s1r = s1v[row];
    float4 Mv = *reinterpret_cast<const float4*>(Mp);

    const unsigned char* Wb = Whb + (long)h * (NN * 256);
    unsigned lof = lane * 8;

    __half2 zero2 = __float2half2_rn(0.f);
    __half2 A0[4] = {zero2, zero2, zero2, zero2};
    __half2 A1[4] = {zero2, zero2, zero2, zero2};
    __half2 A2[4] = {zero2, zero2, zero2, zero2};
    __half2 A3[4] = {zero2, zero2, zero2, zero2};
    float z = 0.f;

#define CVT8(us) (*reinterpret_cast<__half2*>(&(hrtmp = __nv_cvt_fp8x2_to_halfraw2((us), __NV_E4M3))))
    __half2_raw hrtmp;
#define HF4(A, wf, v) { __half2 Wv = __float2half2_rn(wf); \
    A[0] = __hfma2(Wv, CVT8((unsigned short)((v).x & 0xFFFFu)), A[0]); \
    A[1] = __hfma2(Wv, CVT8((unsigned short)((v).x >> 16)),     A[1]); \
    A[2] = __hfma2(Wv, CVT8((unsigned short)((v).y & 0xFFFFu)), A[2]); \
    A[3] = __hfma2(Wv, CVT8((unsigned short)((v).y >> 16)),     A[3]); }

    const float* swf = reinterpret_cast<const float*>(swp);
    for (int base = rs; base < re; base += 384) {
        int n = min(384, re - base);
        __syncthreads();
        for (int e = tid; e < n; e += 256) {
            int j = ci[base + e];
            soff[e] = (unsigned)j << 8;
            float4 s2r = s2v[j];
            float4 w;
            w.x = __expf(lrelu(s1r.x + s2r.x) - Mv.x);
            w.y = __expf(lrelu(s1r.y + s2r.y) - Mv.y);
            w.z = __expf(lrelu(s1r.z + s2r.z) - Mv.z);
            w.w = __expf(lrelu(s1r.w + s2r.w) - Mv.w);
            swp[e] = w;
        }
        if (tid < 8) { soff[n + tid] = 0u; swp[n + tid] = make_float4(0.f, 0.f, 0.f, 0.f); }
        __syncthreads();

        int t = 8 * par;
        if (t < n) {
            float w[8]; uint2 p[8];
#pragma unroll
            for (int i = 0; i < 8; i++) {
                w[i] = swf[(t + i) * 4 + h];
                p[i] = *reinterpret_cast<const uint2*>(Wb + soff[t + i] + lof);
            }
            while (true) {
                uint2 c[8]; float cw[8];
#pragma unroll
                for (int i = 0; i < 8; i++) { c[i] = p[i]; cw[i] = w[i]; }
                t += 16;
                if (t < n) {
#pragma unroll
                    for (int i = 0; i < 8; i++) {
                        w[i] = swf[(t + i) * 4 + h];
                        p[i] = *reinterpret_cast<const uint2*>(Wb + soff[t + i] + lof);
                    }
                }
                z += cw[0] + cw[1] + cw[2] + cw[3] + cw[4] + cw[5] + cw[6] + cw[7];
                HF4(A0, cw[0], c[0]) HF4(A1, cw[1], c[1])
                HF4(A2, cw[2], c[2]) HF4(A3, cw[3], c[3])
                HF4(A0, cw[4], c[4]) HF4(A1, cw[5], c[5])
                HF4(A2, cw[6], c[6]) HF4(A3, cw[7], c[7])
                if (t >= n) break;
            }
        }
    }
#undef HF4
#undef CVT8
#pragma unroll
    for (int k = 0; k < 4; k++) {
        A0[k] = __hadd2(A0[k], A1[k]);
        A2[k] = __hadd2(A2[k], A3[k]);
        A0[k] = __hadd2(A0[k], A2[k]);
    }

    for (int o = 16; o; o >>= 1) z += __shfl_xor_sync(0xFFFFFFFFu, z, o);
    if (lane == 0) szw[warp] = z;

    {
        float2 f0 = __half22float2(A0[0]);
        float2 f1 = __half22float2(A0[1]);
        float2 f2 = __half22float2(A0[2]);
        float2 f3 = __half22float2(A0[3]);
        *reinterpret_cast<float4*>(&sacc[warp][lane * 8]) =
            make_float4(f0.x, f0.y, f1.x, f1.y);
        *reinterpret_cast<float4*>(&sacc[warp][lane * 8 + 4]) =
            make_float4(f2.x, f2.y, f3.x, f3.y);
    }
    __syncthreads();

    if (warp < 4) {
        int hh = warp;
        float Z = szw[2 * hh] + szw[2 * hh + 1];
        float inv = 1.0f / Z;
        float o[8];
#pragma unroll
        for (int k = 0; k < 8; k++) {
            float t = (sacc[2 * hh][lane * 8 + k] + sacc[2 * hh + 1][lane * 8 + k]) * inv;
            o[k] = t > 0.f ? t : expm1f(t);
        }
        uint4 w;
        __nv_bfloat162 p;
        p = __float22bfloat162_rn(make_float2(o[0], o[1])); w.x = *(unsigned int*)&p;
        p = __float22bfloat162_rn(make_float2(o[2], o[3])); w.y = *(unsigned int*)&p;
        p = __float22bfloat162_rn(make_float2(o[4], o[5])); w.z = *(unsigned int*)&p;
        p = __float22bfloat162_rn(make_float2(o[6], o[7])); w.w = *(unsigned int*)&p;
        *reinterpret_cast<uint4*>(outBase + (long)hh * headStride +
                                  (long)row * ostride + lane * 8) = w;
    }
}

// bf16 aggregation (FOUT=64, out layer 0); M decoded from atomic slots
__global__ void k_agg64b(const __nv_bfloat16* __restrict__ Wh,
                         const float* __restrict__ s1, const float* __restrict__ s2,
                         const unsigned* __restrict__ amax,
                         const int* __restrict__ rp, const int* __restrict__ ci,
                         float* __restrict__ out) {
    int row = blockIdx.x, tid = threadIdx.x;
    int tx = tid & 7, ty = tid >> 3;
    __shared__ float sw[258];
    __shared__ unsigned soff[258];
    __shared__ float sacc[2048];
    __shared__ float szr[256];
    float s1i = s1[row];
    float M = lrelu(decf(amax[0]) + decf(amax[1]));
    int rs = rp[row], re = rp[row + 1];
    float acc[8] = {0.f,0.f,0.f,0.f,0.f,0.f,0.f,0.f};
    float z = 0.f;
    unsigned lof = tx * 16;
    for (int base = rs; base < re; base += 256) {
        int n = min(256, re - base);
        __syncthreads();
        if (tid < n) {
            int j = ci[base + tid];
            soff[tid] = (unsigned)j << 7;
            float w = __expf(lrelu(s1i + s2[j]) - M);
            sw[tid] = w;
            z += w;
        }
        __syncthreads();
        for (int t = ty; t < n; t += 32) {
            float w = sw[t];
            uint4 v = *reinterpret_cast<const uint4*>(
                reinterpret_cast<const char*>(Wh) + soff[t] + lof);
#define UNP(u, k0) \
            acc[k0]   = fmaf(w, __uint_as_float((u) << 16),         acc[k0]); \
            acc[k0+1] = fmaf(w, __uint_as_float((u) & 0xFFFF0000u), acc[k0+1]);
            UNP(v.x, 0) UNP(v.y, 2) UNP(v.z, 4) UNP(v.w, 6)
#undef UNP
        }
    }
    szr[tid] = z; __syncthreads();
    for (int s = 128; s; s >>= 1) { if (tid < s) szr[tid] += szr[tid + s]; __syncthreads(); }
    float Z = szr[0];
    *reinterpret_cast<float4*>(&sacc[ty * 64 + tx * 8]) =
        make_float4(acc[0], acc[1], acc[2], acc[3]);
    *reinterpret_cast<float4*>(&sacc[ty * 64 + tx * 8 + 4]) =
        make_float4(acc[4], acc[5], acc[6], acc[7]);
    __syncthreads();
#pragma unroll
    for (int s = 16; s; s >>= 1) {
        if (ty < s) {
            float4* d0 = reinterpret_cast<float4*>(&sacc[ty * 64 + tx * 8]);
            float4* o0 = reinterpret_cast<float4*>(&sacc[(ty + s) * 64 + tx * 8]);
            float4 a = d0[0], b = o0[0];
            a.x += b.x; a.y += b.y; a.z += b.z; a.w += b.w; d0[0] = a;
            float4 c = d0[1], e = o0[1];
            c.x += e.x; c.y += e.y; c.z += e.z; c.w += e.w; d0[1] = c;
        }
        __syncthreads();
    }
    if (ty == 0) {
        float inv = 1.0f / Z;
        float4 a = *reinterpret_cast<const float4*>(&sacc[tx * 8]);
        float4 b = *reinterpret_cast<const float4*>(&sacc[tx * 8 + 4]);
        *reinterpret_cast<float4*>(out + (long)row * 64 + tx * 8) =
            make_float4(a.x * inv, a.y * inv, a.z * inv, a.w * inv);
        *reinterpret_cast<float4*>(out + (long)row * 64 + tx * 8 + 4) =
            make_float4(b.x * inv, b.y * inv, b.z * inv, b.w * inv);
    }
}

// FOUT == 1 aggregation; M from atomic slots
__global__ void k_agg1(const float* __restrict__ whc, const float* __restrict__ s1,
                       const float* __restrict__ s2, const unsigned* __restrict__ amax,
                       const int* __restrict__ rp, const int* __restrict__ ci,
                       float* __restrict__ out) {
    int row = blockIdx.x, tid = threadIdx.x;
    __shared__ float sa[256], szz[256];
    float s1i = s1[row];
    float M = lrelu(decf(amax[2]) + decf(amax[3]));
    int rs = rp[row], re = rp[row + 1];
    float acc = 0.f, z = 0.f;
    for (int e = rs + tid; e < re; e += 256) {
        int j = ci[e];
        float w = __expf(lrelu(s1i + s2[j]) - M);
        z += w;
        acc += w * whc[j];
    }
    sa[tid] = acc; szz[tid] = z; __syncthreads();
    for (int s = 128; s; s >>= 1) {
        if (tid < s) { sa[tid] += sa[tid + s]; szz[tid] += szz[tid + s]; }
        __syncthreads();
    }
    if (tid == 0) out[row] = sa[0] / szz[0];
}

__global__ void k_out1s(const float* __restrict__ h, const float* __restrict__ Wo1,
                        const float* __restrict__ ao1, float* __restrict__ whc,
                        float* __restrict__ s1, float* __restrict__ s2,
                        unsigned* __restrict__ amax) {
    int gw = (blockIdx.x * blockDim.x + threadIdx.x) >> 5;
    int lane = threadIdx.x & 31;
    if (gw >= NN) return;
    float d = 0.f;
    for (int f = lane; f < 64; f += 32) d += h[(long)gw * 64 + f] * Wo1[f];
    for (int o = 16; o; o >>= 1) d += __shfl_xor_sync(0xFFFFFFFFu, d, o);
    if (lane == 0) {
        float d1 = d * ao1[0], d2 = d * ao1[1];
        whc[gw] = d; s1[gw] = d1; s2[gw] = d2;
        atomicMax(&amax[2], encf(d1));
        atomicMax(&amax[3], encf(d2));
    }
}

// ---------------- bf16 tensor-core GEMM, register double-buffered ------------
__device__ __forceinline__ void ldsm4(unsigned& r0, unsigned& r1, unsigned& r2, unsigned& r3,
                                      unsigned addr) {
    asm volatile("ldmatrix.sync.aligned.m8n8.x4.shared.b16 {%0,%1,%2,%3}, [%4];"
                 : "=r"(r0), "=r"(r1), "=r"(r2), "=r"(r3) : "r"(addr));
}
__device__ __forceinline__ void ldsm4t(unsigned& r0, unsigned& r1, unsigned& r2, unsigned& r3,
                                       unsigned addr) {
    asm volatile("ldmatrix.sync.aligned.m8n8.x4.trans.shared.b16 {%0,%1,%2,%3}, [%4];"
                 : "=r"(r0), "=r"(r1), "=r"(r2), "=r"(r3) : "r"(addr));
}
__device__ __forceinline__ void mma16816(float* c, unsigned a0, unsigned a1, unsigned a2,
                                         unsigned a3, unsigned b0, unsigned b1) {
    asm volatile(
        "mma.sync.aligned.m16n8k16.row.col.f32.bf16.bf16.f32 "
        "{%0,%1,%2,%3},{%4,%5,%6,%7},{%8,%9},{%0,%1,%2,%3};"
        : "+f"(c[0]), "+f"(c[1]), "+f"(c[2]), "+f"(c[3])
        : "r"(a0), "r"(a1), "r"(a2), "r"(a3), "r"(b0), "r"(b1));
}

#define GA_ROWB 80
#define GB_ROWB 272
#define GA_BYTES (128 * GA_ROWB)
#define GB_BYTES (32 * GB_ROWB)
#define SBUF (GA_BYTES + GB_BYTES)

__global__ void __launch_bounds__(256, 2) k_bgemm(
    const __nv_bfloat16* __restrict__ A, const __nv_bfloat16* __restrict__ B,
    float* __restrict__ C, unsigned short* __restrict__ C8,
    int M, int N, int K, int lda,
    long sA, long sB, long sC, long sC8) {
    __shared__ __align__(16) unsigned char sm[2 * SBUF];
    A += (long)blockIdx.z * sA;
    B += (long)blockIdx.z * sB;
    if (C) C += (long)blockIdx.z * sC;
    if (C8) C8 += (long)blockIdx.z * sC8;

    int tid = threadIdx.x;
    int warp = tid >> 5, lane = tid & 31;
    int wm = warp & 3, wn = warp >> 2;
    int m0 = blockIdx.y * 128, n0 = blockIdx.x * 128;

    int ar = tid >> 2;
    int ac = tid & 3;
    int br = tid >> 4;
    int bc = tid & 15;
    bool bok = (n0 + bc * 8) < N;

    unsigned s_base = (unsigned)__cvta_generic_to_shared(sm);
    int sub = lane >> 3, r = lane & 7;

    float acc[2][8][4] = {};
    int KT = K / 32;
    uint4 av0, av1, bv0, bv1;
    const uint4 zero4 = make_uint4(0, 0, 0, 0);

    av0 = reinterpret_cast<const uint4*>(A + (long)(m0 + ar) * lda)[ac];
    av1 = reinterpret_cast<const uint4*>(A + (long)(m0 + ar + 64) * lda)[ac];
    bv0 = bok ? *reinterpret_cast<const uint4*>(B + (long)br * N + n0 + bc * 8) : zero4;
    bv1 = bok ? *reinterpret_cast<const uint4*>(B + (long)(br + 16) * N + n0 + bc * 8) : zero4;
    {
        uint4* As4 = reinterpret_cast<uint4*>(sm);
        uint4* Bs4 = reinterpret_cast<uint4*>(sm + GA_BYTES);
        As4[ar * 5 + ac] = av0;
        As4[(ar + 64) * 5 + ac] = av1;
        Bs4[br * 17 + bc] = bv0;
        Bs4[(br + 16) * 17 + bc] = bv1;
    }

    int p = 0;
    for (int it = 0; it < KT; it++) {
        __syncthreads();
        bool more = (it + 1 < KT);
        if (more) {
            int kof = (it + 1) * 32;
            av0 = reinterpret_cast<const uint4*>(A + (long)(m0 + ar) * lda + kof)[ac];
            av1 = reinterpret_cast<const uint4*>(A + (long)(m0 + ar + 64) * lda + kof)[ac];
            bv0 = bok ? *reinterpret_cast<const uint4*>(B + (long)(kof + br) * N + n0 + bc * 8) : zero4;
            bv1 = bok ? *reinterpret_cast<const uint4*>(B + (long)(kof + br + 16) * N + n0 + bc * 8) : zero4;
        }

        unsigned sA_base = s_base + p * SBUF;
        unsigned sB_base = sA_base + GA_BYTES;
#pragma unroll
        for (int ks = 0; ks < 2; ks++) {
            unsigned a[2][4];
#pragma unroll
            for (int i = 0; i < 2; i++) {
                unsigned addr = sA_base
                    + (unsigned)((wm * 32 + i * 16 + (sub & 1) * 8 + r) * GA_ROWB
                                 + ks * 32 + (sub >> 1) * 16);
                ldsm4(a[i][0], a[i][1], a[i][2], a[i][3], addr);
            }
            unsigned b[4][4];
#pragma unroll
            for (int j = 0; j < 4; j++) {
                unsigned addr = sB_base
                    + (unsigned)((ks * 16 + (sub & 1) * 8 + r) * GB_ROWB
                                 + (wn * 64 + j * 16 + (sub >> 1) * 8) * 2);
                ldsm4t(b[j][0], b[j][1], b[j][2], b[j][3], addr);
            }
#pragma unroll
            for (int i = 0; i < 2; i++) {
#pragma unroll
                for (int j = 0; j < 4; j++) {
                    mma16816(acc[i][2 * j],     a[i][0], a[i][1], a[i][2], a[i][3],
                             b[j][0], b[j][1]);
                    mma16816(acc[i][2 * j + 1], a[i][0], a[i][1], a[i][2], a[i][3],
                             b[j][2], b[j][3]);
                }
            }
        }
        if (more) {
            uint4* As4 = reinterpret_cast<uint4*>(sm + (p ^ 1) * SBUF);
            uint4* Bs4 = reinterpret_cast<uint4*>(sm + (p ^ 1) * SBUF + GA_BYTES);
            As4[ar * 5 + ac] = av0;
            As4[(ar + 64) * 5 + ac] = av1;
            Bs4[br * 17 + bc] = bv0;
            Bs4[(br + 16) * 17 + bc] = bv1;
        }
        p ^= 1;
    }

    int g = lane >> 2, ti = lane & 3;
#pragma unroll
    for (int i = 0; i < 2; i++) {
#pragma unroll
        for (int jj = 0; jj < 8; jj++) {
            int row = m0 + wm * 32 + i * 16 + g;
            int col = n0 + wn * 64 + jj * 8 + ti * 2;
            if (col < N) {
                float* c = acc[i][jj];
                if (C) {
                    *reinterpret_cast<float2*>(C + (long)row * N + col) = make_float2(c[0], c[1]);
                    *reinterpret_cast<float2*>(C + (long)(row + 8) * N + col) = make_float2(c[2], c[3]);
                }
                if (C8) {
                    C8[((long)row * N + col) >> 1] =
                        __nv_cvt_float2_to_fp8x2(make_float2(c[0], c[1]), __NV_SATFINITE, __NV_E4M3);
                    C8[((long)(row + 8) * N + col) >> 1] =
                        __nv_cvt_float2_to_fp8x2(make_float2(c[2], c[3]), __NV_SATFINITE, __NV_E4M3);
                }
            }
        }
    }
}

// ---------------- final degree MLP ----------------
__global__ void k_mlp(const float* __restrict__ hout, const float* __restrict__ dv,
                      const float* __restrict__ dW, const float* __restrict__ dW0,
                      const float* __restrict__ dW1, const float* __restrict__ dW01,
                      const float* __restrict__ dW2, const float* __restrict__ dW02,
                      const float* __restrict__ dV, const float* __restrict__ dV0,
                      float* __restrict__ out) {
    int i = blockIdx.x * blockDim.x + threadIdx.x;
    if (i >= NN) return;
    float hv = hout[i];
    float x0 = hv > 0.f ? hv : expm1f(hv);
    float x1 = dv[i];
    float h0[10];
#pragma unroll
    for (int k = 0; k < 10; k++)
        h0[k] = lrelu(x0 * dW[k] + x1 * dW[10 + k] + dW0[k]);
    float h1[20];
#pragma unroll
    for (int k = 0; k < 20; k++) {
        float t = dW01[k];
#pragma unroll
        for (int j = 0; j < 10; j++) t += h0[j] * dW1[j * 20 + k];
        h1[k] = lrelu(t);
    }
    float h2[10];
#pragma unroll
    for (int k = 0; k < 10; k++) {
        float t = dW02[k];
#pragma unroll
        for (int j = 0; j < 20; j++) t += h1[j] * dW2[j * 10 + k];
        h2[k] = lrelu(t);
    }
    float o = dV0[0];
#pragma unroll
    for (int j = 0; j < 10; j++) o += h2[j] * dV[j];
    out[i] = lrelu(o);
}

// ---------------- launch ----------------
extern "C" void kernel_launch(void* const* d_in, const int* in_sizes, int n_in,
                              void* d_out, int out_size) {
    const float* x     = (const float*)d_in[0];
    const float* adj   = (const float*)d_in[1];
    const int*   obs   = (const int*)d_in[2];
    const float* s_mat = (const float*)d_in[3];
    const float* theta = (const float*)d_in[4];
    const float* Wh0   = (const float*)d_in[5];
    const float* ah0   = (const float*)d_in[6];
    const float* Wh1   = (const float*)d_in[7];
    const float* ah1   = (const float*)d_in[8];
    const float* Wo0   = (const float*)d_in[9];
    const float* ao0   = (const float*)d_in[10];
    const float* Wo1   = (const float*)d_in[11];
    const float* ao1   = (const float*)d_in[12];
    const float* dW    = (const float*)d_in[13];
    const float* dW0   = (const float*)d_in[14];
    const float* dW1   = (const float*)d_in[15];
    const float* dW01  = (const float*)d_in[16];
    const float* dW2   = (const float*)d_in[17];
    const float* dW02  = (const float*)d_in[18];
    const float* dV    = (const float*)d_in[19];
    const float* dV0   = (const float*)d_in[20];
    float* out = (float*)d_out;

    float* fa = nullptr;
    int*   ia = nullptr;
    cudaGetSymbolAddress((void**)&fa, g_farena);
    cudaGetSymbolAddress((void**)&ia, g_iarena);

    float* P0   = fa + OFF_P0;
    float* P1   = fa + OFF_P1;
    __nv_bfloat16* oWhb = (__nv_bfloat16*)(fa + OFF_OWH);
    float* ho0  = fa + OFF_HO0;
    float* whc  = fa + OFF_WHC;
    float* hout = fa + OFF_HOUT;
    float* s1v  = fa + OFF_S1V;
    float* s2v  = fa + OFF_S2V;
    float* Mp   = fa + OFF_M;
    float* dv   = fa + OFF_DV;
    float* s1o  = fa + OFF_S1O;
    float* s2o  = fa + OFF_S2O;
    float* part = fa + OFF_PART;
    unsigned char* Whb8  = (unsigned char*)(fa + OFF_WHB);
    __nv_bfloat16* hinb  = (__nv_bfloat16*)(fa + OFF_HINB);
    __nv_bfloat16* h1bb  = (__nv_bfloat16*)(fa + OFF_H1B);
    __nv_bfloat16* hcatb = (__nv_bfloat16*)(fa + OFF_HCATB);
    __nv_bfloat16* W0b   = (__nv_bfloat16*)(fa + OFF_W0B);
    __nv_bfloat16* W1b   = (__nv_bfloat16*)(fa + OFF_W1B);
    __nv_bfloat16* Wo0b  = (__nv_bfloat16*)(fa + OFF_WO0B);
    int* cnt = ia + OFF_CNT;
    int* rp  = ia + OFF_RP;
    unsigned* msk = (unsigned*)(ia + OFF_MSK);
    int* ci  = ia + OFF_CI;
    unsigned* amax = (unsigned*)(ia + OFF_AMAX);

    const long NM = (long)NN * 256;

    static cudaStream_t sAux = nullptr;
    static cudaEvent_t evFork = nullptr, evJoin = nullptr;
    if (sAux == nullptr) {
        cudaStreamCreateWithFlags(&sAux, cudaStreamNonBlocking);
        cudaEventCreateWithFlags(&evFork, cudaEventDisableTiming);
        cudaEventCreateWithFlags(&evJoin, cudaEventDisableTiming);
    }

    // fork: CSR chain + degree on side stream
    cudaEventRecord(evFork, 0);
    cudaStreamWaitEvent(sAux, evFork, 0);
    k_cnt_rs<<<NN, 256, 0, sAux>>>(adj, msk, cnt, s_mat, dv);
    k_scan<<<1, 1024, 0, sAux>>>(cnt, rp);
    k_fill<<<NN, 128, 0, sAux>>>(msk, rp, ci);
    cudaEventRecord(evJoin, sAux);

    // main stream
    k_prep<<<2880, 256>>>((const float4*)x, obs, (const float4*)theta, (uint2*)hinb,
                          (const float4*)Wh0, (uint2*)W0b,
                          (const float4*)Wh1, (uint2*)W1b,
                          (const float4*)Wo0, (uint2*)Wo0b, amax);
    k_wa2<<<dim3(192, 4), 256>>>(Wh0, ah0, P0, Wh1, ah1, P1);
    k_bgemm<<<dim3(2, 32, 4), 256>>>(hinb, W0b, nullptr, (unsigned short*)Whb8,
                                     NN, 256, 512, 512, 0L, 512L * 256, 0L, (long)NN * 128);
    k_sb<<<2048, 256>>>(hinb, 0L, P0, 512, s1v, s2v);
    k_max4<<<4, 512>>>(s1v, s2v, Mp, 4);

    cudaStreamWaitEvent(0, evJoin, 0);

    // ---- head layer 0 aggregation ----
    k_agg4<<<NN, 256>>>(Whb8, (const float4*)s1v, (const float4*)s2v, Mp,
                        rp, ci, h1bb, NM, 256);

    // ---- head layer 1 ----
    k_bgemm<<<dim3(2, 32, 4), 256>>>(h1bb, W1b, nullptr, (unsigned short*)Whb8,
                                     NN, 256, 256, 256, NM, 256L * 256, 0L, (long)NN * 128);
    k_sb<<<2048, 256>>>(h1bb, NM, P1, 256, s1v, s2v);
    k_max4<<<4, 512>>>(s1v, s2v, Mp, 4);
    k_agg4<<<NN, 256>>>(Whb8, (const float4*)s1v, (const float4*)s2v, Mp,
                        rp, ci, hcatb, 256L, 1024);

    // ---- output layer 0 ----
    k_bgemm<<<dim3(1, 32, 4), 256>>>(hcatb, Wo0b, part, nullptr,
                                     NN, 64, 256, 1024, 256L, 256L * 64, 262144L, 0L);
    k_red4s<<<512, 256>>>((const float2*)part, (__nv_bfloat162*)oWhb, ao0, s1o, s2o, amax);
    k_agg64b<<<NN, 256>>>(oWhb, s1o, s2o, amax, rp, ci, ho0);

    // ---- output layer 1 ----
    k_out1s<<<512, 256>>>(ho0, Wo1, ao1, whc, s1o, s2o, amax);
    k_agg1<<<NN, 256>>>(whc, s1o, s2o, amax, rp, ci, hout);

    // ---- elu + degree MLP ----
    k_mlp<<<16, 256>>>(hout, dv, dW, dW0, dW1, dW01, dW2, dW02, dV, dV0, out);
}

// round 14
// speedup vs baseline: 1.5120x; 1.5120x over previous
#include <cuda_runtime.h>
#include <cuda_bf16.h>
#include <cuda_fp8.h>
#include <math.h>

#define NN 4096
#define ALPHA 0.2f

__device__ __forceinline__ float lrelu(float v){ return v >= 0.f ? v : ALPHA * v; }

// monotone float<->uint encoding for atomicMax
__device__ __forceinline__ unsigned encf(float f) {
    unsigned b = __float_as_uint(f);
    return b ^ ((b & 0x80000000u) ? 0xFFFFFFFFu : 0x80000000u);
}
__device__ __forceinline__ float decf(unsigned u) {
    unsigned b = u ^ ((u & 0x80000000u) ? 0x80000000u : 0xFFFFFFFFu);
    return __uint_as_float(b);
}

// ---------------- scratch arenas (device globals; no allocation) -------------
#define OFF_P0    0L
#define OFF_P1    4096L
#define OFF_OWH   8192L
#define OFF_HO0   270336L
#define OFF_WHC   532480L
#define OFF_HOUT  536576L
#define OFF_S1V   540672L
#define OFF_S2V   557056L
#define OFF_M     573440L
#define OFF_DV    573456L
#define OFF_S1O   577552L
#define OFF_S2O   581648L
#define OFF_WHB   585744L     // fp8 4*4096*256 bytes
#define OFF_HINB  1634320L    // bf16 4096*512
#define OFF_H1B   2682896L    // bf16 4*4096*256
#define OFF_HCATB 4780048L    // bf16 4096*1024
#define OFF_W0B   6877200L
#define OFF_W1B   7139344L
#define OFF_WO0B  7270416L
#define OFF_PART  7303184L
#define FARENA_SZ 8400000L

#define OFF_CNT   0
#define OFF_RP    4096
#define OFF_MSK   8208
#define OFF_CI    532496
#define OFF_AMAX  2190000     // 4 encoded-max slots
#define IARENA_SZ 2200000

__device__ float g_farena[FARENA_SZ];
__device__ int   g_iarena[IARENA_SZ];

// ---------------- fused count (adj bitmask) + rowsum (s_mat degree) ----------
__global__ void k_cnt_rs(const float* __restrict__ adj, unsigned* __restrict__ msk,
                         int* __restrict__ cnt,
                         const float* __restrict__ smat, float* __restrict__ dv) {
    int row = blockIdx.x, tid = threadIdx.x;
    int lane = tid & 31, wid = tid >> 5;
    const float4* p = reinterpret_cast<const float4*>(adj + (long)row * NN);
    unsigned* mrow = msk + (long)row * 128;
    int c = 0;
    for (int seg = wid; seg < 32; seg += 8) {
        float4 v = p[seg * 32 + lane];
        unsigned b0 = __ballot_sync(0xFFFFFFFFu, v.x > 0.f);
        unsigned b1 = __ballot_sync(0xFFFFFFFFu, v.y > 0.f);
        unsigned b2 = __ballot_sync(0xFFFFFFFFu, v.z > 0.f);
        unsigned b3 = __ballot_sync(0xFFFFFFFFu, v.w > 0.f);
        c += (v.x > 0.f) + (v.y > 0.f) + (v.z > 0.f) + (v.w > 0.f);
        if (lane == 0) {
            mrow[seg * 4 + 0] = b0; mrow[seg * 4 + 1] = b1;
            mrow[seg * 4 + 2] = b2; mrow[seg * 4 + 3] = b3;
        }
    }
    const float4* q = reinterpret_cast<const float4*>(smat + (long)row * NN);
    float a = 0.f;
    for (int i = tid; i < NN / 4; i += 256) { float4 v = q[i]; a += v.x + v.y + v.z + v.w; }
    for (int o = 16; o; o >>= 1) {
        c += __shfl_xor_sync(0xFFFFFFFFu, c, o);
        a += __shfl_xor_sync(0xFFFFFFFFu, a, o);
    }
    __shared__ int ws[8];
    __shared__ float fs[8];
    if (lane == 0) { ws[wid] = c; fs[wid] = a; }
    __syncthreads();
    if (tid == 0)
        cnt[row] = ws[0] + ws[1] + ws[2] + ws[3] + ws[4] + ws[5] + ws[6] + ws[7];
    if (tid == 32)
        dv[row] = fs[0] + fs[1] + fs[2] + fs[3] + fs[4] + fs[5] + fs[6] + fs[7];
}

__global__ void k_scan(const int* __restrict__ cnt, int* __restrict__ rp) {
    __shared__ int s[1024];
    int t = threadIdx.x;
    int v[4]; int loc = 0;
#pragma unroll
    for (int k = 0; k < 4; k++) { v[k] = cnt[t * 4 + k]; loc += v[k]; }
    s[t] = loc; __syncthreads();
    for (int off = 1; off < 1024; off <<= 1) {
        int add = (t >= off) ? s[t - off] : 0;
        __syncthreads();
        s[t] += add;
        __syncthreads();
    }
    int run = (t == 0) ? 0 : s[t - 1];
#pragma unroll
    for (int k = 0; k < 4; k++) { rp[t * 4 + k] = run; run += v[k]; }
    if (t == 1023) rp[NN] = run;
}

__global__ void k_fill(const unsigned* __restrict__ msk, const int* __restrict__ rp,
                       int* __restrict__ ci) {
    int row = blockIdx.x, tid = threadIdx.x;
    int lane = tid & 31, wid = tid >> 5;
    unsigned m = msk[(long)row * 128 + tid];
    int c = __popc(m);
    int pre = c;
    for (int o = 1; o < 32; o <<= 1) {
        int v = __shfl_up_sync(0xFFFFFFFFu, pre, o);
        if (lane >= o) pre += v;
    }
    __shared__ int wt[4];
    if (lane == 31) wt[wid] = pre;
    __syncthreads();
    int woff = 0;
    for (int i = 0; i < wid; i++) woff += wt[i];
    int pos = rp[row] + woff + pre - c;
    int base = (tid >> 2) * 128 + (tid & 3);
    while (m) {
        int b = __ffs(m) - 1;
        m &= m - 1;
        ci[pos++] = base + b * 4;
    }
}

// ---------------- fused prep: merge->bf16 + 3 weight cvts + amax reset -------
__device__ __forceinline__ uint2 pack_bf16x4(float4 v) {
    __nv_bfloat162 p0 = __float22bfloat162_rn(make_float2(v.x, v.y));
    __nv_bfloat162 p1 = __float22bfloat162_rn(make_float2(v.z, v.w));
    uint2 w;
    w.x = *reinterpret_cast<unsigned int*>(&p0);
    w.y = *reinterpret_cast<unsigned int*>(&p1);
    return w;
}

__global__ void k_prep(const float4* __restrict__ x, const int* __restrict__ obs,
                       const float4* __restrict__ theta, uint2* __restrict__ hinb,
                       const float4* __restrict__ w0, uint2* __restrict__ o0,
                       const float4* __restrict__ w1, uint2* __restrict__ o1,
                       const float4* __restrict__ w2, uint2* __restrict__ o2,
                       unsigned* __restrict__ amax) {
    long i = (long)blockIdx.x * 256 + threadIdx.x;
    if (i < 4) amax[i] = encf(-1e30f);
    if (i < 524288L) {
        int row = (int)(i >> 7);
        int f4 = (int)(i & 127);
        float4 v = x[i];
        if (obs[row] == 1) {
            float4 t = theta[f4];
            v.x += t.x; v.y += t.y; v.z += t.z; v.w += t.w;
        }
        hinb[i] = pack_bf16x4(v);
        return;
    }
    i -= 524288L;
    if (i < 131072) { o0[i] = pack_bf16x4(w0[i]); return; }
    i -= 131072;
    if (i < 65536) { o1[i] = pack_bf16x4(w1[i]); return; }
    i -= 65536;
    if (i < 16384) { o2[i] = pack_bf16x4(w2[i]); }
}

// ---------------- fused W@a for both layers ----------------
__global__ void k_wa2(const float* __restrict__ W0, const float* __restrict__ a0,
                      float* __restrict__ P0,
                      const float* __restrict__ W1, const float* __restrict__ a1,
                      float* __restrict__ P1) {
    int h = blockIdx.y;
    int bx = blockIdx.x;
    const float* W; const float* a; float* P; int Fin;
    if (bx < 128) { W = W0; a = a0; P = P0; Fin = 512; }
    else { W = W1; a = a1; P = P1; Fin = 256; bx -= 128; }
    int idx = bx * 8 + (threadIdx.x >> 5);
    int lane = threadIdx.x & 31;
    if (idx >= 2 * Fin) return;
    int c = idx / Fin, f = idx % Fin;
    const float* wrow = W + ((long)h * Fin + f) * 256;
    const float* av = a + h * 512 + c * 256;
    float d = 0.f;
    for (int k = lane; k < 256; k += 32) d = fmaf(wrow[k], av[k], d);
    for (int o = 16; o; o >>= 1) d += __shfl_xor_sync(0xFFFFFFFFu, d, o);
    if (lane == 0) P[(2 * h + c) * Fin + f] = d;
}

// s1/s2 from bf16 activations -> interleaved [row][head]
__global__ void __launch_bounds__(256) k_sb(
    const __nv_bfloat16* __restrict__ act, long headStride,
    const float* __restrict__ P, int K,
    float* __restrict__ s1, float* __restrict__ s2) {
    __shared__ float Ps[4096];
    int tid = threadIdx.x;
    for (int i = tid; i < 8 * K; i += 256) Ps[i] = P[i];
    __syncthreads();
    int gw = blockIdx.x * 8 + (tid >> 5);
    int lane = tid & 31;
    int row = gw >> 2, h = gw & 3;
    const __nv_bfloat16* a = act + (long)h * headStride + (long)row * K;
    const float* p1 = Ps + (2 * h) * K;
    const float* p2 = p1 + K;
    float d1 = 0.f, d2 = 0.f;
    for (int f = lane * 2; f < K; f += 64) {
        unsigned u = *reinterpret_cast<const unsigned*>(a + f);
        float x0 = __uint_as_float(u << 16);
        float x1 = __uint_as_float(u & 0xFFFF0000u);
        d1 = fmaf(x0, p1[f], fmaf(x1, p1[f + 1], d1));
        d2 = fmaf(x0, p2[f], fmaf(x1, p2[f + 1], d2));
    }
    for (int o = 16; o; o >>= 1) {
        d1 += __shfl_xor_sync(0xFFFFFFFFu, d1, o);
        d2 += __shfl_xor_sync(0xFFFFFFFFu, d2, o);
    }
    if (lane == 0) { s1[gw] = d1; s2[gw] = d2; }
}

// fused split-K reduce + bf16 oWh + s projection + atomic max (out layer 0)
__global__ void k_red4s(const float2* __restrict__ part,
                        __nv_bfloat162* __restrict__ oWhb,
                        const float* __restrict__ ao0,
                        float* __restrict__ s1, float* __restrict__ s2,
                        unsigned* __restrict__ amax) {
    int gw = blockIdx.x * 8 + (threadIdx.x >> 5);
    int lane = threadIdx.x & 31;
    long idx = (long)gw * 32 + lane;
    float2 v0 = part[idx];
    float2 v1 = part[idx + 131072];
    float2 v2 = part[idx + 262144];
    float2 v3 = part[idx + 393216];
    float2 s;
    s.x = v0.x + v1.x + v2.x + v3.x;
    s.y = v0.y + v1.y + v2.y + v3.y;
    oWhb[idx] = __float22bfloat162_rn(s);
    float d1 = s.x * ao0[lane * 2] + s.y * ao0[lane * 2 + 1];
    float d2 = s.x * ao0[64 + lane * 2] + s.y * ao0[64 + lane * 2 + 1];
    for (int o = 16; o; o >>= 1) {
        d1 += __shfl_xor_sync(0xFFFFFFFFu, d1, o);
        d2 += __shfl_xor_sync(0xFFFFFFFFu, d2, o);
    }
    if (lane == 0) {
        s1[gw] = d1; s2[gw] = d2;
        atomicMax(&amax[0], encf(d1));
        atomicMax(&amax[1], encf(d2));
    }
}

// per-head M = leaky(max s1 + max s2); stride-indexed (head layers only)
__global__ void k_max4(const float* __restrict__ s1, const float* __restrict__ s2,
                       float* __restrict__ Mp, int stride) {
    int h = blockIdx.x;
    __shared__ float m1s[512], m2s[512];
    int t = threadIdx.x;
    float m1 = -1e30f, m2 = -1e30f;
    for (int i = t; i < NN; i += 512) {
        m1 = fmaxf(m1, s1[i * stride + h]);
        m2 = fmaxf(m2, s2[i * stride + h]);
    }
    m1s[t] = m1; m2s[t] = m2; __syncthreads();
    for (int s = 256; s; s >>= 1) {
        if (t < s) { m1s[t] = fmaxf(m1s[t], m1s[t + s]); m2s[t] = fmaxf(m2s[t], m2s[t + s]); }
        __syncthreads();
    }
    if (t == 0) Mp[h] = lrelu(m1s[0] + m2s[0]);
}

// ---------- fused 4-head FP8 aggregation: 1 block per row, 2 warps/head ------
// (R12 4-deep pipeline version — fits in 64-reg cap; 8-deep spilled and regressed)
__global__ void __launch_bounds__(256, 4) k_agg4(
    const unsigned char* __restrict__ Whb,
    const float4* __restrict__ s1v, const float4* __restrict__ s2v,
    const float* __restrict__ Mp,
    const int* __restrict__ rp, const int* __restrict__ ci,
    __nv_bfloat16* __restrict__ outBase, long headStride, int ostride) {
    int row = blockIdx.x;
    int tid = threadIdx.x;
    int lane = tid & 31, warp = tid >> 5;
    int h = warp >> 1, par = warp & 1;

    __shared__ float4   swp[392];
    __shared__ unsigned soff[392];
    __shared__ float    sacc[8][256];
    __shared__ float    szw[8];

    int rs = rp[row], re = rp[row + 1];
    float4 s1r = s1v[row];
    float4 Mv = *reinterpret_cast<const float4*>(Mp);

    const unsigned char* Wb = Whb + (long)h * (NN * 256);
    unsigned lof = lane * 8;

    __half2 zero2 = __float2half2_rn(0.f);
    __half2 A0[4] = {zero2, zero2, zero2, zero2};
    __half2 A1[4] = {zero2, zero2, zero2, zero2};
    __half2 A2[4] = {zero2, zero2, zero2, zero2};
    __half2 A3[4] = {zero2, zero2, zero2, zero2};
    float z = 0.f;

#define CVT8(us) (*reinterpret_cast<__half2*>(&(hrtmp = __nv_cvt_fp8x2_to_halfraw2((us), __NV_E4M3))))
    __half2_raw hrtmp;
#define HF4(A, wu, v) { __half2 Wv = *reinterpret_cast<const __half2*>(&(wu)); \
    A[0] = __hfma2(Wv, CVT8((unsigned short)((v).x & 0xFFFFu)), A[0]); \
    A[1] = __hfma2(Wv, CVT8((unsigned short)((v).x >> 16)),     A[1]); \
    A[2] = __hfma2(Wv, CVT8((unsigned short)((v).y & 0xFFFFu)), A[2]); \
    A[3] = __hfma2(Wv, CVT8((unsigned short)((v).y >> 16)),     A[3]); }

    for (int base = rs; base < re; base += 384) {
        int n = min(384, re - base);
        __syncthreads();
        for (int e = tid; e < n; e += 256) {
            int j = ci[base + e];
            soff[e] = (unsigned)j << 8;
            float4 s2r = s2v[j];
            float4 w;
            w.x = __expf(lrelu(s1r.x + s2r.x) - Mv.x);
            w.y = __expf(lrelu(s1r.y + s2r.y) - Mv.y);
            w.z = __expf(lrelu(s1r.z + s2r.z) - Mv.z);
            w.w = __expf(lrelu(s1r.w + s2r.w) - Mv.w);
            swp[e] = w;
        }
        if (tid < 8) { soff[n + tid] = 0u; swp[n + tid] = make_float4(0.f, 0.f, 0.f, 0.f); }
        __syncthreads();

        int t = 4 * par;
        if (t < n) {
            float w0 = reinterpret_cast<const float*>(&swp[t])[h];
            float w1 = reinterpret_cast<const float*>(&swp[t + 1])[h];
            float w2 = reinterpret_cast<const float*>(&swp[t + 2])[h];
            float w3 = reinterpret_cast<const float*>(&swp[t + 3])[h];
            uint2 p0 = *reinterpret_cast<const uint2*>(Wb + soff[t]     + lof);
            uint2 p1 = *reinterpret_cast<const uint2*>(Wb + soff[t + 1] + lof);
            uint2 p2 = *reinterpret_cast<const uint2*>(Wb + soff[t + 2] + lof);
            uint2 p3 = *reinterpret_cast<const uint2*>(Wb + soff[t + 3] + lof);
            while (true) {
                uint2 c0 = p0, c1 = p1, c2 = p2, c3 = p3;
                float cw0 = w0, cw1 = w1, cw2 = w2, cw3 = w3;
                t += 8;
                if (t < n) {
                    w0 = reinterpret_cast<const float*>(&swp[t])[h];
                    w1 = reinterpret_cast<const float*>(&swp[t + 1])[h];
                    w2 = reinterpret_cast<const float*>(&swp[t + 2])[h];
                    w3 = reinterpret_cast<const float*>(&swp[t + 3])[h];
                    p0 = *reinterpret_cast<const uint2*>(Wb + soff[t]     + lof);
                    p1 = *reinterpret_cast<const uint2*>(Wb + soff[t + 1] + lof);
                    p2 = *reinterpret_cast<const uint2*>(Wb + soff[t + 2] + lof);
                    p3 = *reinterpret_cast<const uint2*>(Wb + soff[t + 3] + lof);
                }
                z += cw0 + cw1 + cw2 + cw3;
                __half2 wh0 = __float2half2_rn(cw0);
                __half2 wh1 = __float2half2_rn(cw1);
                __half2 wh2 = __float2half2_rn(cw2);
                __half2 wh3 = __float2half2_rn(cw3);
                HF4(A0, wh0, c0) HF4(A1, wh1, c1) HF4(A2, wh2, c2) HF4(A3, wh3, c3)
                if (t >= n) break;
            }
        }
    }
#undef HF4
#undef CVT8
#pragma unroll
    for (int k = 0; k < 4; k++) {
        A0[k] = __hadd2(A0[k], A1[k]);
        A2[k] = __hadd2(A2[k], A3[k]);
        A0[k] = __hadd2(A0[k], A2[k]);
    }

    for (int o = 16; o; o >>= 1) z += __shfl_xor_sync(0xFFFFFFFFu, z, o);
    if (lane == 0) szw[warp] = z;

    {
        float2 f0 = __half22float2(A0[0]);
        float2 f1 = __half22float2(A0[1]);
        float2 f2 = __half22float2(A0[2]);
        float2 f3 = __half22float2(A0[3]);
        *reinterpret_cast<float4*>(&sacc[warp][lane * 8]) =
            make_float4(f0.x, f0.y, f1.x, f1.y);
        *reinterpret_cast<float4*>(&sacc[warp][lane * 8 + 4]) =
            make_float4(f2.x, f2.y, f3.x, f3.y);
    }
    __syncthreads();

    if (warp < 4) {
        int hh = warp;
        float Z = szw[2 * hh] + szw[2 * hh + 1];
        float inv = 1.0f / Z;
        float o[8];
#pragma unroll
        for (int k = 0; k < 8; k++) {
            float t = (sacc[2 * hh][lane * 8 + k] + sacc[2 * hh + 1][lane * 8 + k]) * inv;
            o[k] = t > 0.f ? t : expm1f(t);
        }
        uint4 w;
        __nv_bfloat162 p;
        p = __float22bfloat162_rn(make_float2(o[0], o[1])); w.x = *(unsigned int*)&p;
        p = __float22bfloat162_rn(make_float2(o[2], o[3])); w.y = *(unsigned int*)&p;
        p = __float22bfloat162_rn(make_float2(o[4], o[5])); w.z = *(unsigned int*)&p;
        p = __float22bfloat162_rn(make_float2(o[6], o[7])); w.w = *(unsigned int*)&p;
        *reinterpret_cast<uint4*>(outBase + (long)hh * headStride +
                                  (long)row * ostride + lane * 8) = w;
    }
}

// bf16 aggregation (FOUT=64, out layer 0); M decoded from atomic slots
__global__ void k_agg64b(const __nv_bfloat16* __restrict__ Wh,
                         const float* __restrict__ s1, const float* __restrict__ s2,
                         const unsigned* __restrict__ amax,
                         const int* __restrict__ rp, const int* __restrict__ ci,
                         float* __restrict__ out) {
    int row = blockIdx.x, tid = threadIdx.x;
    int tx = tid & 7, ty = tid >> 3;
    __shared__ float sw[258];
    __shared__ unsigned soff[258];
    __shared__ float sacc[2048];
    __shared__ float szr[256];
    float s1i = s1[row];
    float M = lrelu(decf(amax[0]) + decf(amax[1]));
    int rs = rp[row], re = rp[row + 1];
    float acc[8] = {0.f,0.f,0.f,0.f,0.f,0.f,0.f,0.f};
    float z = 0.f;
    unsigned lof = tx * 16;
    for (int base = rs; base < re; base += 256) {
        int n = min(256, re - base);
        __syncthreads();
        if (tid < n) {
            int j = ci[base + tid];
            soff[tid] = (unsigned)j << 7;
            float w = __expf(lrelu(s1i + s2[j]) - M);
            sw[tid] = w;
            z += w;
        }
        __syncthreads();
        for (int t = ty; t < n; t += 32) {
            float w = sw[t];
            uint4 v = *reinterpret_cast<const uint4*>(
                reinterpret_cast<const char*>(Wh) + soff[t] + lof);
#define UNP(u, k0) \
            acc[k0]   = fmaf(w, __uint_as_float((u) << 16),         acc[k0]); \
            acc[k0+1] = fmaf(w, __uint_as_float((u) & 0xFFFF0000u), acc[k0+1]);
            UNP(v.x, 0) UNP(v.y, 2) UNP(v.z, 4) UNP(v.w, 6)
#undef UNP
        }
    }
    szr[tid] = z; __syncthreads();
    for (int s = 128; s; s >>= 1) { if (tid < s) szr[tid] += szr[tid + s]; __syncthreads(); }
    float Z = szr[0];
    *reinterpret_cast<float4*>(&sacc[ty * 64 + tx * 8]) =
        make_float4(acc[0], acc[1], acc[2], acc[3]);
    *reinterpret_cast<float4*>(&sacc[ty * 64 + tx * 8 + 4]) =
        make_float4(acc[4], acc[5], acc[6], acc[7]);
    __syncthreads();
#pragma unroll
    for (int s = 16; s; s >>= 1) {
        if (ty < s) {
            float4* d0 = reinterpret_cast<float4*>(&sacc[ty * 64 + tx * 8]);
            float4* o0 = reinterpret_cast<float4*>(&sacc[(ty + s) * 64 + tx * 8]);
            float4 a = d0[0], b = o0[0];
            a.x += b.x; a.y += b.y; a.z += b.z; a.w += b.w; d0[0] = a;
            float4 c = d0[1], e = o0[1];
            c.x += e.x; c.y += e.y; c.z += e.z; c.w += e.w; d0[1] = c;
        }
        __syncthreads();
    }
    if (ty == 0) {
        float inv = 1.0f / Z;
        float4 a = *reinterpret_cast<const float4*>(&sacc[tx * 8]);
        float4 b = *reinterpret_cast<const float4*>(&sacc[tx * 8 + 4]);
        *reinterpret_cast<float4*>(out + (long)row * 64 + tx * 8) =
            make_float4(a.x * inv, a.y * inv, a.z * inv, a.w * inv);
        *reinterpret_cast<float4*>(out + (long)row * 64 + tx * 8 + 4) =
            make_float4(b.x * inv, b.y * inv, b.z * inv, b.w * inv);
    }
}

// FOUT == 1 aggregation; M from atomic slots
__global__ void k_agg1(const float* __restrict__ whc, const float* __restrict__ s1,
                       const float* __restrict__ s2, const unsigned* __restrict__ amax,
                       const int* __restrict__ rp, const int* __restrict__ ci,
                       float* __restrict__ out) {
    int row = blockIdx.x, tid = threadIdx.x;
    __shared__ float sa[256], szz[256];
    float s1i = s1[row];
    float M = lrelu(decf(amax[2]) + decf(amax[3]));
    int rs = rp[row], re = rp[row + 1];
    float acc = 0.f, z = 0.f;
    for (int e = rs + tid; e < re; e += 256) {
        int j = ci[e];
        float w = __expf(lrelu(s1i + s2[j]) - M);
        z += w;
        acc += w * whc[j];
    }
    sa[tid] = acc; szz[tid] = z; __syncthreads();
    for (int s = 128; s; s >>= 1) {
        if (tid < s) { sa[tid] += sa[tid + s]; szz[tid] += szz[tid + s]; }
        __syncthreads();
    }
    if (tid == 0) out[row] = sa[0] / szz[0];
}

__global__ void k_out1s(const float* __restrict__ h, const float* __restrict__ Wo1,
                        const float* __restrict__ ao1, float* __restrict__ whc,
                        float* __restrict__ s1, float* __restrict__ s2,
                        unsigned* __restrict__ amax) {
    int gw = (blockIdx.x * blockDim.x + threadIdx.x) >> 5;
    int lane = threadIdx.x & 31;
    if (gw >= NN) return;
    float d = 0.f;
    for (int f = lane; f < 64; f += 32) d += h[(long)gw * 64 + f] * Wo1[f];
    for (int o = 16; o; o >>= 1) d += __shfl_xor_sync(0xFFFFFFFFu, d, o);
    if (lane == 0) {
        float d1 = d * ao1[0], d2 = d * ao1[1];
        whc[gw] = d; s1[gw] = d1; s2[gw] = d2;
        atomicMax(&amax[2], encf(d1));
        atomicMax(&amax[3], encf(d2));
    }
}

// ---------------- bf16 tensor-core GEMM, register double-buffered ------------
__device__ __forceinline__ void ldsm4(unsigned& r0, unsigned& r1, unsigned& r2, unsigned& r3,
                                      unsigned addr) {
    asm volatile("ldmatrix.sync.aligned.m8n8.x4.shared.b16 {%0,%1,%2,%3}, [%4];"
                 : "=r"(r0), "=r"(r1), "=r"(r2), "=r"(r3) : "r"(addr));
}
__device__ __forceinline__ void ldsm4t(unsigned& r0, unsigned& r1, unsigned& r2, unsigned& r3,
                                       unsigned addr) {
    asm volatile("ldmatrix.sync.aligned.m8n8.x4.trans.shared.b16 {%0,%1,%2,%3}, [%4];"
                 : "=r"(r0), "=r"(r1), "=r"(r2), "=r"(r3) : "r"(addr));
}
__device__ __forceinline__ void mma16816(float* c, unsigned a0, unsigned a1, unsigned a2,
                                         unsigned a3, unsigned b0, unsigned b1) {
    asm volatile(
        "mma.sync.aligned.m16n8k16.row.col.f32.bf16.bf16.f32 "
        "{%0,%1,%2,%3},{%4,%5,%6,%7},{%8,%9},{%0,%1,%2,%3};"
        : "+f"(c[0]), "+f"(c[1]), "+f"(c[2]), "+f"(c[3])
        : "r"(a0), "r"(a1), "r"(a2), "r"(a3), "r"(b0), "r"(b1));
}

#define GA_ROWB 80
#define GB_ROWB 272
#define GA_BYTES (128 * GA_ROWB)
#define GB_BYTES (32 * GB_ROWB)
#define SBUF (GA_BYTES + GB_BYTES)

__global__ void __launch_bounds__(256, 2) k_bgemm(
    const __nv_bfloat16* __restrict__ A, const __nv_bfloat16* __restrict__ B,
    float* __restrict__ C, unsigned short* __restrict__ C8,
    int M, int N, int K, int lda,
    long sA, long sB, long sC, long sC8) {
    __shared__ __align__(16) unsigned char sm[2 * SBUF];
    A += (long)blockIdx.z * sA;
    B += (long)blockIdx.z * sB;
    if (C) C += (long)blockIdx.z * sC;
    if (C8) C8 += (long)blockIdx.z * sC8;

    int tid = threadIdx.x;
    int warp = tid >> 5, lane = tid & 31;
    int wm = warp & 3, wn = warp >> 2;
    int m0 = blockIdx.y * 128, n0 = blockIdx.x * 128;

    int ar = tid >> 2;
    int ac = tid & 3;
    int br = tid >> 4;
    int bc = tid & 15;
    bool bok = (n0 + bc * 8) < N;

    unsigned s_base = (unsigned)__cvta_generic_to_shared(sm);
    int sub = lane >> 3, r = lane & 7;

    float acc[2][8][4] = {};
    int KT = K / 32;
    uint4 av0, av1, bv0, bv1;
    const uint4 zero4 = make_uint4(0, 0, 0, 0);

    av0 = reinterpret_cast<const uint4*>(A + (long)(m0 + ar) * lda)[ac];
    av1 = reinterpret_cast<const uint4*>(A + (long)(m0 + ar + 64) * lda)[ac];
    bv0 = bok ? *reinterpret_cast<const uint4*>(B + (long)br * N + n0 + bc * 8) : zero4;
    bv1 = bok ? *reinterpret_cast<const uint4*>(B + (long)(br + 16) * N + n0 + bc * 8) : zero4;
    {
        uint4* As4 = reinterpret_cast<uint4*>(sm);
        uint4* Bs4 = reinterpret_cast<uint4*>(sm + GA_BYTES);
        As4[ar * 5 + ac] = av0;
        As4[(ar + 64) * 5 + ac] = av1;
        Bs4[br * 17 + bc] = bv0;
        Bs4[(br + 16) * 17 + bc] = bv1;
    }

    int p = 0;
    for (int it = 0; it < KT; it++) {
        __syncthreads();
        bool more = (it + 1 < KT);
        if (more) {
            int kof = (it + 1) * 32;
            av0 = reinterpret_cast<const uint4*>(A + (long)(m0 + ar) * lda + kof)[ac];
            av1 = reinterpret_cast<const uint4*>(A + (long)(m0 + ar + 64) * lda + kof)[ac];
            bv0 = bok ? *reinterpret_cast<const uint4*>(B + (long)(kof + br) * N + n0 + bc * 8) : zero4;
            bv1 = bok ? *reinterpret_cast<const uint4*>(B + (long)(kof + br + 16) * N + n0 + bc * 8) : zero4;
        }

        unsigned sA_base = s_base + p * SBUF;
        unsigned sB_base = sA_base + GA_BYTES;
#pragma unroll
        for (int ks = 0; ks < 2; ks++) {
            unsigned a[2][4];
#pragma unroll
            for (int i = 0; i < 2; i++) {
                unsigned addr = sA_base
                    + (unsigned)((wm * 32 + i * 16 + (sub & 1) * 8 + r) * GA_ROWB
                                 + ks * 32 + (sub >> 1) * 16);
                ldsm4(a[i][0], a[i][1], a[i][2], a[i][3], addr);
            }
            unsigned b[4][4];
#pragma unroll
            for (int j = 0; j < 4; j++) {
                unsigned addr = sB_base
                    + (unsigned)((ks * 16 + (sub & 1) * 8 + r) * GB_ROWB
                                 + (wn * 64 + j * 16 + (sub >> 1) * 8) * 2);
                ldsm4t(b[j][0], b[j][1], b[j][2], b[j][3], addr);
            }
#pragma unroll
            for (int i = 0; i < 2; i++) {
#pragma unroll
                for (int j = 0; j < 4; j++) {
                    mma16816(acc[i][2 * j],     a[i][0], a[i][1], a[i][2], a[i][3],
                             b[j][0], b[j][1]);
                    mma16816(acc[i][2 * j + 1], a[i][0], a[i][1], a[i][2], a[i][3],
                             b[j][2], b[j][3]);
                }
            }
        }
        if (more) {
            uint4* As4 = reinterpret_cast<uint4*>(sm + (p ^ 1) * SBUF);
            uint4* Bs4 = reinterpret_cast<uint4*>(sm + (p ^ 1) * SBUF + GA_BYTES);
            As4[ar * 5 + ac] = av0;
            As4[(ar + 64) * 5 + ac] = av1;
            Bs4[br * 17 + bc] = bv0;
            Bs4[(br + 16) * 17 + bc] = bv1;
        }
        p ^= 1;
    }

    int g = lane >> 2, ti = lane & 3;
#pragma unroll
    for (int i = 0; i < 2; i++) {
#pragma unroll
        for (int jj = 0; jj < 8; jj++) {
            int row = m0 + wm * 32 + i * 16 + g;
            int col = n0 + wn * 64 + jj * 8 + ti * 2;
            if (col < N) {
                float* c = acc[i][jj];
                if (C) {
                    *reinterpret_cast<float2*>(C + (long)row * N + col) = make_float2(c[0], c[1]);
                    *reinterpret_cast<float2*>(C + (long)(row + 8) * N + col) = make_float2(c[2], c[3]);
                }
                if (C8) {
                    C8[((long)row * N + col) >> 1] =
                        __nv_cvt_float2_to_fp8x2(make_float2(c[0], c[1]), __NV_SATFINITE, __NV_E4M3);
                    C8[((long)(row + 8) * N + col) >> 1] =
                        __nv_cvt_float2_to_fp8x2(make_float2(c[2], c[3]), __NV_SATFINITE, __NV_E4M3);
                }
            }
        }
    }
}

// ---------------- final degree MLP ----------------
__global__ void k_mlp(const float* __restrict__ hout, const float* __restrict__ dv,
                      const float* __restrict__ dW, const float* __restrict__ dW0,
                      const float* __restrict__ dW1, const float* __restrict__ dW01,
                      const float* __restrict__ dW2, const float* __restrict__ dW02,
                      const float* __restrict__ dV, const float* __restrict__ dV0,
                      float* __restrict__ out) {
    int i = blockIdx.x * blockDim.x + threadIdx.x;
    if (i >= NN) return;
    float hv = hout[i];
    float x0 = hv > 0.f ? hv : expm1f(hv);
    float x1 = dv[i];
    float h0[10];
#pragma unroll
    for (int k = 0; k < 10; k++)
        h0[k] = lrelu(x0 * dW[k] + x1 * dW[10 + k] + dW0[k]);
    float h1[20];
#pragma unroll
    for (int k = 0; k < 20; k++) {
        float t = dW01[k];
#pragma unroll
        for (int j = 0; j < 10; j++) t += h0[j] * dW1[j * 20 + k];
        h1[k] = lrelu(t);
    }
    float h2[10];
#pragma unroll
    for (int k = 0; k < 10; k++) {
        float t = dW02[k];
#pragma unroll
        for (int j = 0; j < 20; j++) t += h1[j] * dW2[j * 10 + k];
        h2[k] = lrelu(t);
    }
    float o = dV0[0];
#pragma unroll
    for (int j = 0; j < 10; j++) o += h2[j] * dV[j];
    out[i] = lrelu(o);
}

// ---------------- launch ----------------
extern "C" void kernel_launch(void* const* d_in, const int* in_sizes, int n_in,
                              void* d_out, int out_size) {
    const float* x     = (const float*)d_in[0];
    const float* adj   = (const float*)d_in[1];
    const int*   obs   = (const int*)d_in[2];
    const float* s_mat = (const float*)d_in[3];
    const float* theta = (const float*)d_in[4];
    const float* Wh0   = (const float*)d_in[5];
    const float* ah0   = (const float*)d_in[6];
    const float* Wh1   = (const float*)d_in[7];
    const float* ah1   = (const float*)d_in[8];
    const float* Wo0   = (const float*)d_in[9];
    const float* ao0   = (const float*)d_in[10];
    const float* Wo1   = (const float*)d_in[11];
    const float* ao1   = (const float*)d_in[12];
    const float* dW    = (const float*)d_in[13];
    const float* dW0   = (const float*)d_in[14];
    const float* dW1   = (const float*)d_in[15];
    const float* dW01  = (const float*)d_in[16];
    const float* dW2   = (const float*)d_in[17];
    const float* dW02  = (const float*)d_in[18];
    const float* dV    = (const float*)d_in[19];
    const float* dV0   = (const float*)d_in[20];
    float* out = (float*)d_out;

    float* fa = nullptr;
    int*   ia = nullptr;
    cudaGetSymbolAddress((void**)&fa, g_farena);
    cudaGetSymbolAddress((void**)&ia, g_iarena);

    float* P0   = fa + OFF_P0;
    float* P1   = fa + OFF_P1;
    __nv_bfloat16* oWhb = (__nv_bfloat16*)(fa + OFF_OWH);
    float* ho0  = fa + OFF_HO0;
    float* whc  = fa + OFF_WHC;
    float* hout = fa + OFF_HOUT;
    float* s1v  = fa + OFF_S1V;
    float* s2v  = fa + OFF_S2V;
    float* Mp   = fa + OFF_M;
    float* dv   = fa + OFF_DV;
    float* s1o  = fa + OFF_S1O;
    float* s2o  = fa + OFF_S2O;
    float* part = fa + OFF_PART;
    unsigned char* Whb8  = (unsigned char*)(fa + OFF_WHB);
    __nv_bfloat16* hinb  = (__nv_bfloat16*)(fa + OFF_HINB);
    __nv_bfloat16* h1bb  = (__nv_bfloat16*)(fa + OFF_H1B);
    __nv_bfloat16* hcatb = (__nv_bfloat16*)(fa + OFF_HCATB);
    __nv_bfloat16* W0b   = (__nv_bfloat16*)(fa + OFF_W0B);
    __nv_bfloat16* W1b   = (__nv_bfloat16*)(fa + OFF_W1B);
    __nv_bfloat16* Wo0b  = (__nv_bfloat16*)(fa + OFF_WO0B);
    int* cnt = ia + OFF_CNT;
    int* rp  = ia + OFF_RP;
    unsigned* msk = (unsigned*)(ia + OFF_MSK);
    int* ci  = ia + OFF_CI;
    unsigned* amax = (unsigned*)(ia + OFF_AMAX);

    const long NM = (long)NN * 256;

    static cudaStream_t sAux = nullptr;
    static cudaEvent_t evFork = nullptr, evJoin = nullptr;
    if (sAux == nullptr) {
        cudaStreamCreateWithFlags(&sAux, cudaStreamNonBlocking);
        cudaEventCreateWithFlags(&evFork, cudaEventDisableTiming);
        cudaEventCreateWithFlags(&evJoin, cudaEventDisableTiming);
    }

    // fork: CSR chain + degree on side stream
    cudaEventRecord(evFork, 0);
    cudaStreamWaitEvent(sAux, evFork, 0);
    k_cnt_rs<<<NN, 256, 0, sAux>>>(adj, msk, cnt, s_mat, dv);
    k_scan<<<1, 1024, 0, sAux>>>(cnt, rp);
    k_fill<<<NN, 128, 0, sAux>>>(msk, rp, ci);
    cudaEventRecord(evJoin, sAux);

    // main stream
    k_prep<<<2880, 256>>>((const float4*)x, obs, (const float4*)theta, (uint2*)hinb,
                          (const float4*)Wh0, (uint2*)W0b,
                          (const float4*)Wh1, (uint2*)W1b,
                          (const float4*)Wo0, (uint2*)Wo0b, amax);
    k_wa2<<<dim3(192, 4), 256>>>(Wh0, ah0, P0, Wh1, ah1, P1);
    k_bgemm<<<dim3(2, 32, 4), 256>>>(hinb, W0b, nullptr, (unsigned short*)Whb8,
                                     NN, 256, 512, 512, 0L, 512L * 256, 0L, (long)NN * 128);
    k_sb<<<2048, 256>>>(hinb, 0L, P0, 512, s1v, s2v);
    k_max4<<<4, 512>>>(s1v, s2v, Mp, 4);

    cudaStreamWaitEvent(0, evJoin, 0);

    // ---- head layer 0 aggregation ----
    k_agg4<<<NN, 256>>>(Whb8, (const float4*)s1v, (const float4*)s2v, Mp,
                        rp, ci, h1bb, NM, 256);

    // ---- head layer 1 ----
    k_bgemm<<<dim3(2, 32, 4), 256>>>(h1bb, W1b, nullptr, (unsigned short*)Whb8,
                                     NN, 256, 256, 256, NM, 256L * 256, 0L, (long)NN * 128);
    k_sb<<<2048, 256>>>(h1bb, NM, P1, 256, s1v, s2v);
    k_max4<<<4, 512>>>(s1v, s2v, Mp, 4);
    k_agg4<<<NN, 256>>>(Whb8, (const float4*)s1v, (const float4*)s2v, Mp,
                        rp, ci, hcatb, 256L, 1024);

    // ---- output layer 0 ----
    k_bgemm<<<dim3(1, 32, 4), 256>>>(hcatb, Wo0b, part, nullptr,
                                     NN, 64, 256, 1024, 256L, 256L * 64, 262144L, 0L);
    k_red4s<<<512, 256>>>((const float2*)part, (__nv_bfloat162*)oWhb, ao0, s1o, s2o, amax);
    k_agg64b<<<NN, 256>>>(oWhb, s1o, s2o, amax, rp, ci, ho0);

    // ---- output layer 1 ----
    k_out1s<<<512, 256>>>(ho0, Wo1, ao1, whc, s1o, s2o, amax);
    k_agg1<<<NN, 256>>>(whc, s1o, s2o, amax, rp, ci, hout);

    // ---- elu + degree MLP ----
    k_mlp<<<16, 256>>>(hout, dv, dW, dW0, dW1, dW01, dW2, dW02, dV, dV0, out);
}

// round 15
// speedup vs baseline: 1.5684x; 1.0373x over previous
#include <cuda_runtime.h>
#include <cuda_bf16.h>
#include <cuda_fp8.h>
#include <math.h>

#define NN 4096
#define ALPHA 0.2f

__device__ __forceinline__ float lrelu(float v){ return v >= 0.f ? v : ALPHA * v; }

// monotone float<->uint encoding for atomicMax
__device__ __forceinline__ unsigned encf(float f) {
    unsigned b = __float_as_uint(f);
    return b ^ ((b & 0x80000000u) ? 0xFFFFFFFFu : 0x80000000u);
}
__device__ __forceinline__ float decf(unsigned u) {
    unsigned b = u ^ ((u & 0x80000000u) ? 0x80000000u : 0xFFFFFFFFu);
    return __uint_as_float(b);
}

// ---------------- scratch arenas (device globals; no allocation) -------------
#define OFF_P0    0L
#define OFF_P1    4096L
#define OFF_OWH   8192L
#define OFF_HO0   270336L
#define OFF_WHC   532480L
#define OFF_HOUT  536576L
#define OFF_S1V   540672L
#define OFF_S2V   557056L
#define OFF_M     573440L
#define OFF_DV    573456L
#define OFF_S1O   577552L
#define OFF_S2O   581648L
#define OFF_WHB   585744L     // fp8 4*4096*256 bytes
#define OFF_HINB  1634320L    // bf16 4096*512
#define OFF_H1B   2682896L    // bf16 4*4096*256
#define OFF_HCATB 4780048L    // bf16 4096*1024
#define OFF_W0B   6877200L
#define OFF_W1B   7139344L
#define OFF_WO0B  7270416L
#define OFF_PART  7303184L
#define FARENA_SZ 8400000L

#define OFF_CNT   0
#define OFF_RP    4096
#define OFF_MSK   8208
#define OFF_CI    532496
#define OFF_AMAX  2190000     // 4 encoded-max slots
#define IARENA_SZ 2200000

__device__ float g_farena[FARENA_SZ];
__device__ int   g_iarena[IARENA_SZ];

// ---------------- fused count (adj bitmask) + rowsum (s_mat degree) ----------
__global__ void k_cnt_rs(const float* __restrict__ adj, unsigned* __restrict__ msk,
                         int* __restrict__ cnt,
                         const float* __restrict__ smat, float* __restrict__ dv) {
    int row = blockIdx.x, tid = threadIdx.x;
    int lane = tid & 31, wid = tid >> 5;
    const float4* p = reinterpret_cast<const float4*>(adj + (long)row * NN);
    unsigned* mrow = msk + (long)row * 128;
    int c = 0;
    for (int seg = wid; seg < 32; seg += 8) {
        float4 v = p[seg * 32 + lane];
        unsigned b0 = __ballot_sync(0xFFFFFFFFu, v.x > 0.f);
        unsigned b1 = __ballot_sync(0xFFFFFFFFu, v.y > 0.f);
        unsigned b2 = __ballot_sync(0xFFFFFFFFu, v.z > 0.f);
        unsigned b3 = __ballot_sync(0xFFFFFFFFu, v.w > 0.f);
        c += (v.x > 0.f) + (v.y > 0.f) + (v.z > 0.f) + (v.w > 0.f);
        if (lane == 0) {
            mrow[seg * 4 + 0] = b0; mrow[seg * 4 + 1] = b1;
            mrow[seg * 4 + 2] = b2; mrow[seg * 4 + 3] = b3;
        }
    }
    const float4* q = reinterpret_cast<const float4*>(smat + (long)row * NN);
    float a = 0.f;
    for (int i = tid; i < NN / 4; i += 256) { float4 v = q[i]; a += v.x + v.y + v.z + v.w; }
    for (int o = 16; o; o >>= 1) {
        c += __shfl_xor_sync(0xFFFFFFFFu, c, o);
        a += __shfl_xor_sync(0xFFFFFFFFu, a, o);
    }
    __shared__ int ws[8];
    __shared__ float fs[8];
    if (lane == 0) { ws[wid] = c; fs[wid] = a; }
    __syncthreads();
    if (tid == 0)
        cnt[row] = ws[0] + ws[1] + ws[2] + ws[3] + ws[4] + ws[5] + ws[6] + ws[7];
    if (tid == 32)
        dv[row] = fs[0] + fs[1] + fs[2] + fs[3] + fs[4] + fs[5] + fs[6] + fs[7];
}

__global__ void k_scan(const int* __restrict__ cnt, int* __restrict__ rp) {
    __shared__ int s[1024];
    int t = threadIdx.x;
    int v[4]; int loc = 0;
#pragma unroll
    for (int k = 0; k < 4; k++) { v[k] = cnt[t * 4 + k]; loc += v[k]; }
    s[t] = loc; __syncthreads();
    for (int off = 1; off < 1024; off <<= 1) {
        int add = (t >= off) ? s[t - off] : 0;
        __syncthreads();
        s[t] += add;
        __syncthreads();
    }
    int run = (t == 0) ? 0 : s[t - 1];
#pragma unroll
    for (int k = 0; k < 4; k++) { rp[t * 4 + k] = run; run += v[k]; }
    if (t == 1023) rp[NN] = run;
}

__global__ void k_fill(const unsigned* __restrict__ msk, const int* __restrict__ rp,
                       int* __restrict__ ci) {
    int row = blockIdx.x, tid = threadIdx.x;
    int lane = tid & 31, wid = tid >> 5;
    unsigned m = msk[(long)row * 128 + tid];
    int c = __popc(m);
    int pre = c;
    for (int o = 1; o < 32; o <<= 1) {
        int v = __shfl_up_sync(0xFFFFFFFFu, pre, o);
        if (lane >= o) pre += v;
    }
    __shared__ int wt[4];
    if (lane == 31) wt[wid] = pre;
    __syncthreads();
    int woff = 0;
    for (int i = 0; i < wid; i++) woff += wt[i];
    int pos = rp[row] + woff + pre - c;
    int base = (tid >> 2) * 128 + (tid & 3);
    while (m) {
        int b = __ffs(m) - 1;
        m &= m - 1;
        ci[pos++] = base + b * 4;
    }
}

// ---------------- fused prep: merge->bf16 + 3 weight cvts + amax reset -------
__device__ __forceinline__ uint2 pack_bf16x4(float4 v) {
    __nv_bfloat162 p0 = __float22bfloat162_rn(make_float2(v.x, v.y));
    __nv_bfloat162 p1 = __float22bfloat162_rn(make_float2(v.z, v.w));
    uint2 w;
    w.x = *reinterpret_cast<unsigned int*>(&p0);
    w.y = *reinterpret_cast<unsigned int*>(&p1);
    return w;
}

__global__ void k_prep(const float4* __restrict__ x, const int* __restrict__ obs,
                       const float4* __restrict__ theta, uint2* __restrict__ hinb,
                       const float4* __restrict__ w0, uint2* __restrict__ o0,
                       const float4* __restrict__ w1, uint2* __restrict__ o1,
                       const float4* __restrict__ w2, uint2* __restrict__ o2,
                       unsigned* __restrict__ amax) {
    long i = (long)blockIdx.x * 256 + threadIdx.x;
    if (i < 4) amax[i] = encf(-1e30f);
    if (i < 524288L) {
        int row = (int)(i >> 7);
        int f4 = (int)(i & 127);
        float4 v = x[i];
        if (obs[row] == 1) {
            float4 t = theta[f4];
            v.x += t.x; v.y += t.y; v.z += t.z; v.w += t.w;
        }
        hinb[i] = pack_bf16x4(v);
        return;
    }
    i -= 524288L;
    if (i < 131072) { o0[i] = pack_bf16x4(w0[i]); return; }
    i -= 131072;
    if (i < 65536) { o1[i] = pack_bf16x4(w1[i]); return; }
    i -= 65536;
    if (i < 16384) { o2[i] = pack_bf16x4(w2[i]); }
}

// ---------------- fused W@a for both layers ----------------
__global__ void k_wa2(const float* __restrict__ W0, const float* __restrict__ a0,
                      float* __restrict__ P0,
                      const float* __restrict__ W1, const float* __restrict__ a1,
                      float* __restrict__ P1) {
    int h = blockIdx.y;
    int bx = blockIdx.x;
    const float* W; const float* a; float* P; int Fin;
    if (bx < 128) { W = W0; a = a0; P = P0; Fin = 512; }
    else { W = W1; a = a1; P = P1; Fin = 256; bx -= 128; }
    int idx = bx * 8 + (threadIdx.x >> 5);
    int lane = threadIdx.x & 31;
    if (idx >= 2 * Fin) return;
    int c = idx / Fin, f = idx % Fin;
    const float* wrow = W + ((long)h * Fin + f) * 256;
    const float* av = a + h * 512 + c * 256;
    float d = 0.f;
    for (int k = lane; k < 256; k += 32) d = fmaf(wrow[k], av[k], d);
    for (int o = 16; o; o >>= 1) d += __shfl_xor_sync(0xFFFFFFFFu, d, o);
    if (lane == 0) P[(2 * h + c) * Fin + f] = d;
}

// s1/s2 from bf16 activations -> interleaved [row][head]
__global__ void __launch_bounds__(256) k_sb(
    const __nv_bfloat16* __restrict__ act, long headStride,
    const float* __restrict__ P, int K,
    float* __restrict__ s1, float* __restrict__ s2) {
    __shared__ float Ps[4096];
    int tid = threadIdx.x;
    for (int i = tid; i < 8 * K; i += 256) Ps[i] = P[i];
    __syncthreads();
    int gw = blockIdx.x * 8 + (tid >> 5);
    int lane = tid & 31;
    int row = gw >> 2, h = gw & 3;
    const __nv_bfloat16* a = act + (long)h * headStride + (long)row * K;
    const float* p1 = Ps + (2 * h) * K;
    const float* p2 = p1 + K;
    float d1 = 0.f, d2 = 0.f;
    for (int f = lane * 2; f < K; f += 64) {
        unsigned u = *reinterpret_cast<const unsigned*>(a + f);
        float x0 = __uint_as_float(u << 16);
        float x1 = __uint_as_float(u & 0xFFFF0000u);
        d1 = fmaf(x0, p1[f], fmaf(x1, p1[f + 1], d1));
        d2 = fmaf(x0, p2[f], fmaf(x1, p2[f + 1], d2));
    }
    for (int o = 16; o; o >>= 1) {
        d1 += __shfl_xor_sync(0xFFFFFFFFu, d1, o);
        d2 += __shfl_xor_sync(0xFFFFFFFFu, d2, o);
    }
    if (lane == 0) { s1[gw] = d1; s2[gw] = d2; }
}

// fused split-K reduce + bf16 oWh + s projection + atomic max (out layer 0)
__global__ void k_red4s(const float2* __restrict__ part,
                        __nv_bfloat162* __restrict__ oWhb,
                        const float* __restrict__ ao0,
                        float* __restrict__ s1, float* __restrict__ s2,
                        unsigned* __restrict__ amax) {
    int gw = blockIdx.x * 8 + (threadIdx.x >> 5);
    int lane = threadIdx.x & 31;
    long idx = (long)gw * 32 + lane;
    float2 v0 = part[idx];
    float2 v1 = part[idx + 131072];
    float2 v2 = part[idx + 262144];
    float2 v3 = part[idx + 393216];
    float2 s;
    s.x = v0.x + v1.x + v2.x + v3.x;
    s.y = v0.y + v1.y + v2.y + v3.y;
    oWhb[idx] = __float22bfloat162_rn(s);
    float d1 = s.x * ao0[lane * 2] + s.y * ao0[lane * 2 + 1];
    float d2 = s.x * ao0[64 + lane * 2] + s.y * ao0[64 + lane * 2 + 1];
    for (int o = 16; o; o >>= 1) {
        d1 += __shfl_xor_sync(0xFFFFFFFFu, d1, o);
        d2 += __shfl_xor_sync(0xFFFFFFFFu, d2, o);
    }
    if (lane == 0) {
        s1[gw] = d1; s2[gw] = d2;
        atomicMax(&amax[0], encf(d1));
        atomicMax(&amax[1], encf(d2));
    }
}

// per-head M = leaky(max s1 + max s2); stride-indexed (head layers only)
__global__ void k_max4(const float* __restrict__ s1, const float* __restrict__ s2,
                       float* __restrict__ Mp, int stride) {
    int h = blockIdx.x;
    __shared__ float m1s[512], m2s[512];
    int t = threadIdx.x;
    float m1 = -1e30f, m2 = -1e30f;
    for (int i = t; i < NN; i += 512) {
        m1 = fmaxf(m1, s1[i * stride + h]);
        m2 = fmaxf(m2, s2[i * stride + h]);
    }
    m1s[t] = m1; m2s[t] = m2; __syncthreads();
    for (int s = 256; s; s >>= 1) {
        if (t < s) { m1s[t] = fmaxf(m1s[t], m1s[t + s]); m2s[t] = fmaxf(m2s[t], m2s[t + s]); }
        __syncthreads();
    }
    if (t == 0) Mp[h] = lrelu(m1s[0] + m2s[0]);
}

// ---------- fused 4-head FP8 aggregation: 1 block per row, 2 warps/head ------
__global__ void __launch_bounds__(256, 4) k_agg4(
    const unsigned char* __restrict__ Whb,
    const float4* __restrict__ s1v, const float4* __restrict__ s2v,
    const float* __restrict__ Mp,
    const int* __restrict__ rp, const int* __restrict__ ci,
    __nv_bfloat16* __restrict__ outBase, long headStride, int ostride) {
    int row = blockIdx.x;
    int tid = threadIdx.x;
    int lane = tid & 31, warp = tid >> 5;
    int h = warp >> 1, par = warp & 1;

    __shared__ float4   swp[392];
    __shared__ unsigned soff[392];
    __shared__ float    sacc[8][256];
    __shared__ float    szw[8];

    int rs = rp[row], re = rp[row + 1];
    float4 s1r = s1v[row];
    float4 Mv = *reinterpret_cast<const float4*>(Mp);

    const unsigned char* Wb = Whb + (long)h * (NN * 256);
    unsigned lof = lane * 8;

    __half2 zero2 = __float2half2_rn(0.f);
    __half2 A0[4] = {zero2, zero2, zero2, zero2};
    __half2 A1[4] = {zero2, zero2, zero2, zero2};
    __half2 A2[4] = {zero2, zero2, zero2, zero2};
    __half2 A3[4] = {zero2, zero2, zero2, zero2};
    float z = 0.f;

#define CVT8(us) (*reinterpret_cast<__half2*>(&(hrtmp = __nv_cvt_fp8x2_to_halfraw2((us), __NV_E4M3))))
    __half2_raw hrtmp;
#define HF4(A, wu, v) { __half2 Wv = *reinterpret_cast<const __half2*>(&(wu)); \
    A[0] = __hfma2(Wv, CVT8((unsigned short)((v).x & 0xFFFFu)), A[0]); \
    A[1] = __hfma2(Wv, CVT8((unsigned short)((v).x >> 16)),     A[1]); \
    A[2] = __hfma2(Wv, CVT8((unsigned short)((v).y & 0xFFFFu)), A[2]); \
    A[3] = __hfma2(Wv, CVT8((unsigned short)((v).y >> 16)),     A[3]); }

    for (int base = rs; base < re; base += 384) {
        int n = min(384, re - base);
        __syncthreads();
        for (int e = tid; e < n; e += 256) {
            int j = ci[base + e];
            soff[e] = (unsigned)j << 8;
            float4 s2r = s2v[j];
            float4 w;
            w.x = __expf(lrelu(s1r.x + s2r.x) - Mv.x);
            w.y = __expf(lrelu(s1r.y + s2r.y) - Mv.y);
            w.z = __expf(lrelu(s1r.z + s2r.z) - Mv.z);
            w.w = __expf(lrelu(s1r.w + s2r.w) - Mv.w);
            swp[e] = w;
        }
        if (tid < 8) { soff[n + tid] = 0u; swp[n + tid] = make_float4(0.f, 0.f, 0.f, 0.f); }
        __syncthreads();

        int t = 4 * par;
        if (t < n) {
            float w0 = reinterpret_cast<const float*>(&swp[t])[h];
            float w1 = reinterpret_cast<const float*>(&swp[t + 1])[h];
            float w2 = reinterpret_cast<const float*>(&swp[t + 2])[h];
            float w3 = reinterpret_cast<const float*>(&swp[t + 3])[h];
            uint2 p0 = *reinterpret_cast<const uint2*>(Wb + soff[t]     + lof);
            uint2 p1 = *reinterpret_cast<const uint2*>(Wb + soff[t + 1] + lof);
            uint2 p2 = *reinterpret_cast<const uint2*>(Wb + soff[t + 2] + lof);
            uint2 p3 = *reinterpret_cast<const uint2*>(Wb + soff[t + 3] + lof);
            while (true) {
                uint2 c0 = p0, c1 = p1, c2 = p2, c3 = p3;
                float cw0 = w0, cw1 = w1, cw2 = w2, cw3 = w3;
                t += 8;
                if (t < n) {
                    w0 = reinterpret_cast<const float*>(&swp[t])[h];
                    w1 = reinterpret_cast<const float*>(&swp[t + 1])[h];
                    w2 = reinterpret_cast<const float*>(&swp[t + 2])[h];
                    w3 = reinterpret_cast<const float*>(&swp[t + 3])[h];
                    p0 = *reinterpret_cast<const uint2*>(Wb + soff[t]     + lof);
                    p1 = *reinterpret_cast<const uint2*>(Wb + soff[t + 1] + lof);
                    p2 = *reinterpret_cast<const uint2*>(Wb + soff[t + 2] + lof);
                    p3 = *reinterpret_cast<const uint2*>(Wb + soff[t + 3] + lof);
                }
                z += cw0 + cw1 + cw2 + cw3;
                __half2 wh0 = __float2half2_rn(cw0);
                __half2 wh1 = __float2half2_rn(cw1);
                __half2 wh2 = __float2half2_rn(cw2);
                __half2 wh3 = __float2half2_rn(cw3);
                HF4(A0, wh0, c0) HF4(A1, wh1, c1) HF4(A2, wh2, c2) HF4(A3, wh3, c3)
                if (t >= n) break;
            }
        }
    }
#undef HF4
#undef CVT8
#pragma unroll
    for (int k = 0; k < 4; k++) {
        A0[k] = __hadd2(A0[k], A1[k]);
        A2[k] = __hadd2(A2[k], A3[k]);
        A0[k] = __hadd2(A0[k], A2[k]);
    }

    for (int o = 16; o; o >>= 1) z += __shfl_xor_sync(0xFFFFFFFFu, z, o);
    if (lane == 0) szw[warp] = z;

    {
        float2 f0 = __half22float2(A0[0]);
        float2 f1 = __half22float2(A0[1]);
        float2 f2 = __half22float2(A0[2]);
        float2 f3 = __half22float2(A0[3]);
        *reinterpret_cast<float4*>(&sacc[warp][lane * 8]) =
            make_float4(f0.x, f0.y, f1.x, f1.y);
        *reinterpret_cast<float4*>(&sacc[warp][lane * 8 + 4]) =
            make_float4(f2.x, f2.y, f3.x, f3.y);
    }
    __syncthreads();

    if (warp < 4) {
        int hh = warp;
        float Z = szw[2 * hh] + szw[2 * hh + 1];
        float inv = 1.0f / Z;
        float o[8];
#pragma unroll
        for (int k = 0; k < 8; k++) {
            float t = (sacc[2 * hh][lane * 8 + k] + sacc[2 * hh + 1][lane * 8 + k]) * inv;
            o[k] = t > 0.f ? t : expm1f(t);
        }
        uint4 w;
        __nv_bfloat162 p;
        p = __float22bfloat162_rn(make_float2(o[0], o[1])); w.x = *(unsigned int*)&p;
        p = __float22bfloat162_rn(make_float2(o[2], o[3])); w.y = *(unsigned int*)&p;
        p = __float22bfloat162_rn(make_float2(o[4], o[5])); w.z = *(unsigned int*)&p;
        p = __float22bfloat162_rn(make_float2(o[6], o[7])); w.w = *(unsigned int*)&p;
        *reinterpret_cast<uint4*>(outBase + (long)hh * headStride +
                                  (long)row * ostride + lane * 8) = w;
    }
}

// bf16 aggregation (FOUT=64, out layer 0); M decoded from atomic slots
__global__ void k_agg64b(const __nv_bfloat16* __restrict__ Wh,
                         const float* __restrict__ s1, const float* __restrict__ s2,
                         const unsigned* __restrict__ amax,
                         const int* __restrict__ rp, const int* __restrict__ ci,
                         float* __restrict__ out) {
    int row = blockIdx.x, tid = threadIdx.x;
    int tx = tid & 7, ty = tid >> 3;
    __shared__ float sw[258];
    __shared__ unsigned soff[258];
    __shared__ float sacc[2048];
    __shared__ float szr[256];
    float s1i = s1[row];
    float M = lrelu(decf(amax[0]) + decf(amax[1]));
    int rs = rp[row], re = rp[row + 1];
    float acc[8] = {0.f,0.f,0.f,0.f,0.f,0.f,0.f,0.f};
    float z = 0.f;
    unsigned lof = tx * 16;
    for (int base = rs; base < re; base += 256) {
        int n = min(256, re - base);
        __syncthreads();
        if (tid < n) {
            int j = ci[base + tid];
            soff[tid] = (unsigned)j << 7;
            float w = __expf(lrelu(s1i + s2[j]) - M);
            sw[tid] = w;
            z += w;
        }
        __syncthreads();
        for (int t = ty; t < n; t += 32) {
            float w = sw[t];
            uint4 v = *reinterpret_cast<const uint4*>(
                reinterpret_cast<const char*>(Wh) + soff[t] + lof);
#define UNP(u, k0) \
            acc[k0]   = fmaf(w, __uint_as_float((u) << 16),         acc[k0]); \
            acc[k0+1] = fmaf(w, __uint_as_float((u) & 0xFFFF0000u), acc[k0+1]);
            UNP(v.x, 0) UNP(v.y, 2) UNP(v.z, 4) UNP(v.w, 6)
#undef UNP
        }
    }
    szr[tid] = z; __syncthreads();
    for (int s = 128; s; s >>= 1) { if (tid < s) szr[tid] += szr[tid + s]; __syncthreads(); }
    float Z = szr[0];
    *reinterpret_cast<float4*>(&sacc[ty * 64 + tx * 8]) =
        make_float4(acc[0], acc[1], acc[2], acc[3]);
    *reinterpret_cast<float4*>(&sacc[ty * 64 + tx * 8 + 4]) =
        make_float4(acc[4], acc[5], acc[6], acc[7]);
    __syncthreads();
#pragma unroll
    for (int s = 16; s; s >>= 1) {
        if (ty < s) {
            float4* d0 = reinterpret_cast<float4*>(&sacc[ty * 64 + tx * 8]);
            float4* o0 = reinterpret_cast<float4*>(&sacc[(ty + s) * 64 + tx * 8]);
            float4 a = d0[0], b = o0[0];
            a.x += b.x; a.y += b.y; a.z += b.z; a.w += b.w; d0[0] = a;
            float4 c = d0[1], e = o0[1];
            c.x += e.x; c.y += e.y; c.z += e.z; c.w += e.w; d0[1] = c;
        }
        __syncthreads();
    }
    if (ty == 0) {
        float inv = 1.0f / Z;
        float4 a = *reinterpret_cast<const float4*>(&sacc[tx * 8]);
        float4 b = *reinterpret_cast<const float4*>(&sacc[tx * 8 + 4]);
        *reinterpret_cast<float4*>(out + (long)row * 64 + tx * 8) =
            make_float4(a.x * inv, a.y * inv, a.z * inv, a.w * inv);
        *reinterpret_cast<float4*>(out + (long)row * 64 + tx * 8 + 4) =
            make_float4(b.x * inv, b.y * inv, b.z * inv, b.w * inv);
    }
}

// FOUT == 1 aggregation; M from atomic slots
__global__ void k_agg1(const float* __restrict__ whc, const float* __restrict__ s1,
                       const float* __restrict__ s2, const unsigned* __restrict__ amax,
                       const int* __restrict__ rp, const int* __restrict__ ci,
                       float* __restrict__ out) {
    int row = blockIdx.x, tid = threadIdx.x;
    __shared__ float sa[256], szz[256];
    float s1i = s1[row];
    float M = lrelu(decf(amax[2]) + decf(amax[3]));
    int rs = rp[row], re = rp[row + 1];
    float acc = 0.f, z = 0.f;
    for (int e = rs + tid; e < re; e += 256) {
        int j = ci[e];
        float w = __expf(lrelu(s1i + s2[j]) - M);
        z += w;
        acc += w * whc[j];
    }
    sa[tid] = acc; szz[tid] = z; __syncthreads();
    for (int s = 128; s; s >>= 1) {
        if (tid < s) { sa[tid] += sa[tid + s]; szz[tid] += szz[tid + s]; }
        __syncthreads();
    }
    if (tid == 0) out[row] = sa[0] / szz[0];
}

__global__ void k_out1s(const float* __restrict__ h, const float* __restrict__ Wo1,
                        const float* __restrict__ ao1, float* __restrict__ whc,
                        float* __restrict__ s1, float* __restrict__ s2,
                        unsigned* __restrict__ amax) {
    int gw = (blockIdx.x * blockDim.x + threadIdx.x) >> 5;
    int lane = threadIdx.x & 31;
    if (gw >= NN) return;
    float d = 0.f;
    for (int f = lane; f < 64; f += 32) d += h[(long)gw * 64 + f] * Wo1[f];
    for (int o = 16; o; o >>= 1) d += __shfl_xor_sync(0xFFFFFFFFu, d, o);
    if (lane == 0) {
        float d1 = d * ao1[0], d2 = d * ao1[1];
        whc[gw] = d; s1[gw] = d1; s2[gw] = d2;
        atomicMax(&amax[2], encf(d1));
        atomicMax(&amax[3], encf(d2));
    }
}

// ---------------- bf16 tensor-core GEMM, register double-buffered ------------
__device__ __forceinline__ void ldsm4(unsigned& r0, unsigned& r1, unsigned& r2, unsigned& r3,
                                      unsigned addr) {
    asm volatile("ldmatrix.sync.aligned.m8n8.x4.shared.b16 {%0,%1,%2,%3}, [%4];"
                 : "=r"(r0), "=r"(r1), "=r"(r2), "=r"(r3) : "r"(addr));
}
__device__ __forceinline__ void ldsm4t(unsigned& r0, unsigned& r1, unsigned& r2, unsigned& r3,
                                       unsigned addr) {
    asm volatile("ldmatrix.sync.aligned.m8n8.x4.trans.shared.b16 {%0,%1,%2,%3}, [%4];"
                 : "=r"(r0), "=r"(r1), "=r"(r2), "=r"(r3) : "r"(addr));
}
__device__ __forceinline__ void mma16816(float* c, unsigned a0, unsigned a1, unsigned a2,
                                         unsigned a3, unsigned b0, unsigned b1) {
    asm volatile(
        "mma.sync.aligned.m16n8k16.row.col.f32.bf16.bf16.f32 "
        "{%0,%1,%2,%3},{%4,%5,%6,%7},{%8,%9},{%0,%1,%2,%3};"
        : "+f"(c[0]), "+f"(c[1]), "+f"(c[2]), "+f"(c[3])
        : "r"(a0), "r"(a1), "r"(a2), "r"(a3), "r"(b0), "r"(b1));
}

#define GA_ROWB 80
#define GB_ROWB 272
#define GA_BYTES (128 * GA_ROWB)
#define GB_BYTES (32 * GB_ROWB)
#define SBUF (GA_BYTES + GB_BYTES)

__global__ void __launch_bounds__(256, 2) k_bgemm(
    const __nv_bfloat16* __restrict__ A, const __nv_bfloat16* __restrict__ B,
    float* __restrict__ C, unsigned short* __restrict__ C8,
    int M, int N, int K, int lda,
    long sA, long sB, long sC, long sC8) {
    __shared__ __align__(16) unsigned char sm[2 * SBUF];
    A += (long)blockIdx.z * sA;
    B += (long)blockIdx.z * sB;
    if (C) C += (long)blockIdx.z * sC;
    if (C8) C8 += (long)blockIdx.z * sC8;

    int tid = threadIdx.x;
    int warp = tid >> 5, lane = tid & 31;
    int wm = warp & 3, wn = warp >> 2;
    int m0 = blockIdx.y * 128, n0 = blockIdx.x * 128;

    int ar = tid >> 2;
    int ac = tid & 3;
    int br = tid >> 4;
    int bc = tid & 15;
    bool bok = (n0 + bc * 8) < N;

    unsigned s_base = (unsigned)__cvta_generic_to_shared(sm);
    int sub = lane >> 3, r = lane & 7;

    float acc[2][8][4] = {};
    int KT = K / 32;
    uint4 av0, av1, bv0, bv1;
    const uint4 zero4 = make_uint4(0, 0, 0, 0);

    av0 = reinterpret_cast<const uint4*>(A + (long)(m0 + ar) * lda)[ac];
    av1 = reinterpret_cast<const uint4*>(A + (long)(m0 + ar + 64) * lda)[ac];
    bv0 = bok ? *reinterpret_cast<const uint4*>(B + (long)br * N + n0 + bc * 8) : zero4;
    bv1 = bok ? *reinterpret_cast<const uint4*>(B + (long)(br + 16) * N + n0 + bc * 8) : zero4;
    {
        uint4* As4 = reinterpret_cast<uint4*>(sm);
        uint4* Bs4 = reinterpret_cast<uint4*>(sm + GA_BYTES);
        As4[ar * 5 + ac] = av0;
        As4[(ar + 64) * 5 + ac] = av1;
        Bs4[br * 17 + bc] = bv0;
        Bs4[(br + 16) * 17 + bc] = bv1;
    }

    int p = 0;
    for (int it = 0; it < KT; it++) {
        __syncthreads();
        bool more = (it + 1 < KT);
        if (more) {
            int kof = (it + 1) * 32;
            av0 = reinterpret_cast<const uint4*>(A + (long)(m0 + ar) * lda + kof)[ac];
            av1 = reinterpret_cast<const uint4*>(A + (long)(m0 + ar + 64) * lda + kof)[ac];
            bv0 = bok ? *reinterpret_cast<const uint4*>(B + (long)(kof + br) * N + n0 + bc * 8) : zero4;
            bv1 = bok ? *reinterpret_cast<const uint4*>(B + (long)(kof + br + 16) * N + n0 + bc * 8) : zero4;
        }

        unsigned sA_base = s_base + p * SBUF;
        unsigned sB_base = sA_base + GA_BYTES;
#pragma unroll
        for (int ks = 0; ks < 2; ks++) {
            unsigned a[2][4];
#pragma unroll
            for (int i = 0; i < 2; i++) {
                unsigned addr = sA_base
                    + (unsigned)((wm * 32 + i * 16 + (sub & 1) * 8 + r) * GA_ROWB
                                 + ks * 32 + (sub >> 1) * 16);
                ldsm4(a[i][0], a[i][1], a[i][2], a[i][3], addr);
            }
            unsigned b[4][4];
#pragma unroll
            for (int j = 0; j < 4; j++) {
                unsigned addr = sB_base
                    + (unsigned)((ks * 16 + (sub & 1) * 8 + r) * GB_ROWB
                                 + (wn * 64 + j * 16 + (sub >> 1) * 8) * 2);
                ldsm4t(b[j][0], b[j][1], b[j][2], b[j][3], addr);
            }
#pragma unroll
            for (int i = 0; i < 2; i++) {
#pragma unroll
                for (int j = 0; j < 4; j++) {
                    mma16816(acc[i][2 * j],     a[i][0], a[i][1], a[i][2], a[i][3],
                             b[j][0], b[j][1]);
                    mma16816(acc[i][2 * j + 1], a[i][0], a[i][1], a[i][2], a[i][3],
                             b[j][2], b[j][3]);
                }
            }
        }
        if (more) {
            uint4* As4 = reinterpret_cast<uint4*>(sm + (p ^ 1) * SBUF);
            uint4* Bs4 = reinterpret_cast<uint4*>(sm + (p ^ 1) * SBUF + GA_BYTES);
            As4[ar * 5 + ac] = av0;
            As4[(ar + 64) * 5 + ac] = av1;
            Bs4[br * 17 + bc] = bv0;
            Bs4[(br + 16) * 17 + bc] = bv1;
        }
        p ^= 1;
    }

    int g = lane >> 2, ti = lane & 3;
#pragma unroll
    for (int i = 0; i < 2; i++) {
#pragma unroll
        for (int jj = 0; jj < 8; jj++) {
            int row = m0 + wm * 32 + i * 16 + g;
            int col = n0 + wn * 64 + jj * 8 + ti * 2;
            if (col < N) {
                float* c = acc[i][jj];
                if (C) {
                    *reinterpret_cast<float2*>(C + (long)row * N + col) = make_float2(c[0], c[1]);
                    *reinterpret_cast<float2*>(C + (long)(row + 8) * N + col) = make_float2(c[2], c[3]);
                }
                if (C8) {
                    C8[((long)row * N + col) >> 1] =
                        __nv_cvt_float2_to_fp8x2(make_float2(c[0], c[1]), __NV_SATFINITE, __NV_E4M3);
                    C8[((long)(row + 8) * N + col) >> 1] =
                        __nv_cvt_float2_to_fp8x2(make_float2(c[2], c[3]), __NV_SATFINITE, __NV_E4M3);
                }
            }
        }
    }
}

// ---------------- final degree MLP ----------------
__global__ void k_mlp(const float* __restrict__ hout, const float* __restrict__ dv,
                      const float* __restrict__ dW, const float* __restrict__ dW0,
                      const float* __restrict__ dW1, const float* __restrict__ dW01,
                      const float* __restrict__ dW2, const float* __restrict__ dW02,
                      const float* __restrict__ dV, const float* __restrict__ dV0,
                      float* __restrict__ out) {
    int i = blockIdx.x * blockDim.x + threadIdx.x;
    if (i >= NN) return;
    float hv = hout[i];
    float x0 = hv > 0.f ? hv : expm1f(hv);
    float x1 = dv[i];
    float h0[10];
#pragma unroll
    for (int k = 0; k < 10; k++)
        h0[k] = lrelu(x0 * dW[k] + x1 * dW[10 + k] + dW0[k]);
    float h1[20];
#pragma unroll
    for (int k = 0; k < 20; k++) {
        float t = dW01[k];
#pragma unroll
        for (int j = 0; j < 10; j++) t += h0[j] * dW1[j * 20 + k];
        h1[k] = lrelu(t);
    }
    float h2[10];
#pragma unroll
    for (int k = 0; k < 10; k++) {
        float t = dW02[k];
#pragma unroll
        for (int j = 0; j < 20; j++) t += h1[j] * dW2[j * 10 + k];
        h2[k] = lrelu(t);
    }
    float o = dV0[0];
#pragma unroll
    for (int j = 0; j < 10; j++) o += h2[j] * dV[j];
    out[i] = lrelu(o);
}

// ---------------- launch ----------------
extern "C" void kernel_launch(void* const* d_in, const int* in_sizes, int n_in,
                              void* d_out, int out_size) {
    const float* x     = (const float*)d_in[0];
    const float* adj   = (const float*)d_in[1];
    const int*   obs   = (const int*)d_in[2];
    const float* s_mat = (const float*)d_in[3];
    const float* theta = (const float*)d_in[4];
    const float* Wh0   = (const float*)d_in[5];
    const float* ah0   = (const float*)d_in[6];
    const float* Wh1   = (const float*)d_in[7];
    const float* ah1   = (const float*)d_in[8];
    const float* Wo0   = (const float*)d_in[9];
    const float* ao0   = (const float*)d_in[10];
    const float* Wo1   = (const float*)d_in[11];
    const float* ao1   = (const float*)d_in[12];
    const float* dW    = (const float*)d_in[13];
    const float* dW0   = (const float*)d_in[14];
    const float* dW1   = (const float*)d_in[15];
    const float* dW01  = (const float*)d_in[16];
    const float* dW2   = (const float*)d_in[17];
    const float* dW02  = (const float*)d_in[18];
    const float* dV    = (const float*)d_in[19];
    const float* dV0   = (const float*)d_in[20];
    float* out = (float*)d_out;

    float* fa = nullptr;
    int*   ia = nullptr;
    cudaGetSymbolAddress((void**)&fa, g_farena);
    cudaGetSymbolAddress((void**)&ia, g_iarena);

    float* P0   = fa + OFF_P0;
    float* P1   = fa + OFF_P1;
    __nv_bfloat16* oWhb = (__nv_bfloat16*)(fa + OFF_OWH);
    float* ho0  = fa + OFF_HO0;
    float* whc  = fa + OFF_WHC;
    float* hout = fa + OFF_HOUT;
    float* s1v  = fa + OFF_S1V;
    float* s2v  = fa + OFF_S2V;
    float* Mp   = fa + OFF_M;
    float* dv   = fa + OFF_DV;
    float* s1o  = fa + OFF_S1O;
    float* s2o  = fa + OFF_S2O;
    float* part = fa + OFF_PART;
    unsigned char* Whb8  = (unsigned char*)(fa + OFF_WHB);
    __nv_bfloat16* hinb  = (__nv_bfloat16*)(fa + OFF_HINB);
    __nv_bfloat16* h1bb  = (__nv_bfloat16*)(fa + OFF_H1B);
    __nv_bfloat16* hcatb = (__nv_bfloat16*)(fa + OFF_HCATB);
    __nv_bfloat16* W0b   = (__nv_bfloat16*)(fa + OFF_W0B);
    __nv_bfloat16* W1b   = (__nv_bfloat16*)(fa + OFF_W1B);
    __nv_bfloat16* Wo0b  = (__nv_bfloat16*)(fa + OFF_WO0B);
    int* cnt = ia + OFF_CNT;
    int* rp  = ia + OFF_RP;
    unsigned* msk = (unsigned*)(ia + OFF_MSK);
    int* ci  = ia + OFF_CI;
    unsigned* amax = (unsigned*)(ia + OFF_AMAX);

    const long NM = (long)NN * 256;

    static cudaStream_t sAux = nullptr;
    static cudaEvent_t evFork = nullptr, evPrep = nullptr, evS0 = nullptr,
                       evA0 = nullptr, evS1 = nullptr;
    if (sAux == nullptr) {
        cudaStreamCreateWithFlags(&sAux, cudaStreamNonBlocking);
        cudaEventCreateWithFlags(&evFork, cudaEventDisableTiming);
        cudaEventCreateWithFlags(&evPrep, cudaEventDisableTiming);
        cudaEventCreateWithFlags(&evS0, cudaEventDisableTiming);
        cudaEventCreateWithFlags(&evA0, cudaEventDisableTiming);
        cudaEventCreateWithFlags(&evS1, cudaEventDisableTiming);
    }

    // fork: CSR chain + degree on side stream (independent of GEMM path)
    cudaEventRecord(evFork, 0);
    cudaStreamWaitEvent(sAux, evFork, 0);
    k_cnt_rs<<<NN, 256, 0, sAux>>>(adj, msk, cnt, s_mat, dv);
    k_scan<<<1, 1024, 0, sAux>>>(cnt, rp);
    k_fill<<<NN, 128, 0, sAux>>>(msk, rp, ci);

    // main stream: prep + projections
    k_prep<<<2880, 256>>>((const float4*)x, obs, (const float4*)theta, (uint2*)hinb,
                          (const float4*)Wh0, (uint2*)W0b,
                          (const float4*)Wh1, (uint2*)W1b,
                          (const float4*)Wo0, (uint2*)Wo0b, amax);
    k_wa2<<<dim3(192, 4), 256>>>(Wh0, ah0, P0, Wh1, ah1, P1);
    cudaEventRecord(evPrep, 0);

    // side stream (after CSR + prep): s-path L0 concurrent with GEMM L0
    cudaStreamWaitEvent(sAux, evPrep, 0);
    k_sb<<<2048, 256, 0, sAux>>>(hinb, 0L, P0, 512, s1v, s2v);
    k_max4<<<4, 512, 0, sAux>>>(s1v, s2v, Mp, 4);
    cudaEventRecord(evS0, sAux);

    // main: GEMM L0
    k_bgemm<<<dim3(2, 32, 4), 256>>>(hinb, W0b, nullptr, (unsigned short*)Whb8,
                                     NN, 256, 512, 512, 0L, 512L * 256, 0L, (long)NN * 128);

    // join: agg L0 needs s-path + CSR (evS0 is ordered after k_fill on sAux)
    cudaStreamWaitEvent(0, evS0, 0);
    k_agg4<<<NN, 256>>>(Whb8, (const float4*)s1v, (const float4*)s2v, Mp,
                        rp, ci, h1bb, NM, 256);
    cudaEventRecord(evA0, 0);

    // side stream: s-path L1 (reads h1bb, writes s1v/s2v/Mp after agg L0 done)
    cudaStreamWaitEvent(sAux, evA0, 0);
    k_sb<<<2048, 256, 0, sAux>>>(h1bb, NM, P1, 256, s1v, s2v);
    k_max4<<<4, 512, 0, sAux>>>(s1v, s2v, Mp, 4);
    cudaEventRecord(evS1, sAux);

    // main: GEMM L1 concurrent with s-path L1
    k_bgemm<<<dim3(2, 32, 4), 256>>>(h1bb, W1b, nullptr, (unsigned short*)Whb8,
                                     NN, 256, 256, 256, NM, 256L * 256, 0L, (long)NN * 128);
    cudaStreamWaitEvent(0, evS1, 0);
    k_agg4<<<NN, 256>>>(Whb8, (const float4*)s1v, (const float4*)s2v, Mp,
                        rp, ci, hcatb, 256L, 1024);

    // ---- output layer 0 ----
    k_bgemm<<<dim3(1, 32, 4), 256>>>(hcatb, Wo0b, part, nullptr,
                                     NN, 64, 256, 1024, 256L, 256L * 64, 262144L, 0L);
    k_red4s<<<512, 256>>>((const float2*)part, (__nv_bfloat162*)oWhb, ao0, s1o, s2o, amax);
    k_agg64b<<<NN, 256>>>(oWhb, s1o, s2o, amax, rp, ci, ho0);

    // ---- output layer 1 ----
    k_out1s<<<512, 256>>>(ho0, Wo1, ao1, whc, s1o, s2o, amax);
    k_agg1<<<NN, 256>>>(whc, s1o, s2o, amax, rp, ci, hout);

    // ---- elu + degree MLP ----
    k_mlp<<<16, 256>>>(hout, dv, dW, dW0, dW1, dW01, dW2, dW02, dV, dV0, out);
}